// round 14
// baseline (speedup 1.0000x reference)
#include <cuda_runtime.h>
#include <cuda_fp16.h>
#include <math.h>
#include <stdint.h>

// ---------------- problem constants ----------------
#define NN_AG 2048
#define HID   2048
#define OBS_D 1024
#define ACT_D 64
#define ITERS 3

// ---------------- device scratch ----------------
// fragment-major packed fp16 operands; one 8KB block = 128 rows x 32 k
// DOUBLE-BUFFERED: epilogue packs next-iter h while siblings read current buffer.
__device__ __align__(16) __half g_ApackA[(size_t)16 * 128 * 4096];
__device__ __align__(16) __half g_ApackB[(size_t)16 * 128 * 4096];
__device__ __align__(16) __half g_Aobs [(size_t)16 * 32  * 4096]; // obs
__device__ __align__(16) __half g_Wcat [(size_t)64 * 128 * 4096]; // gate-interleaved [w_ih|w_hh]
__device__ __align__(16) __half g_Wenc [(size_t)16 * 32  * 4096]; // enc_w
__device__ float g_e   [(size_t)NN_AG * HID];
__device__ float g_h   [(size_t)NN_AG * HID];
__device__ float g_cell[(size_t)NN_AG * HID];
__device__ float g_part[16 * HID];
__device__ float g_S   [HID];
__device__ float g_bsum[4 * HID];
__device__ float g_nalive;

#define STAGE_B 16384          // [A 8K][B 8K], BK=32
#define NSTG 5
// epilogue needs zbuf(128*132*4=67584) + sh(128*33*4=16896) = 84480 > 5*16384
#define SMEM_DYN 84480

__device__ __forceinline__ float sigf(float x) { return 1.0f / (1.0f + expf(-x)); }

// ---------------- low-level helpers ----------------
__device__ __forceinline__ uint32_t smem_u32(const void* p) {
    uint32_t a;
    asm("{ .reg .u64 t; cvta.to.shared.u64 t, %1; cvt.u32.u64 %0, t; }" : "=r"(a) : "l"(p));
    return a;
}
__device__ __forceinline__ void cpasync16(uint32_t d, const void* s) {
    asm volatile("cp.async.cg.shared.global [%0], [%1], 16;" :: "r"(d), "l"(s));
}
__device__ __forceinline__ uint4 lds128(uint32_t a) {
    uint4 v;
    asm volatile("ld.shared.v4.b32 {%0,%1,%2,%3}, [%4];"
                 : "=r"(v.x), "=r"(v.y), "=r"(v.z), "=r"(v.w) : "r"(a));
    return v;
}
__device__ __forceinline__ uint2 lds64(uint32_t a) {
    uint2 v;
    asm volatile("ld.shared.v2.b32 {%0,%1}, [%2];" : "=r"(v.x), "=r"(v.y) : "r"(a));
    return v;
}
__device__ __forceinline__ void mma16816(float* c, const uint32_t* a, const uint32_t* b) {
    asm volatile(
        "mma.sync.aligned.m16n8k16.row.col.f32.f16.f16.f32 "
        "{%0,%1,%2,%3}, {%4,%5,%6,%7}, {%8,%9}, {%0,%1,%2,%3};"
        : "+f"(c[0]), "+f"(c[1]), "+f"(c[2]), "+f"(c[3])
        : "r"(a[0]), "r"(a[1]), "r"(a[2]), "r"(a[3]), "r"(b[0]), "r"(b[1]));
}
__device__ __forceinline__ uint32_t hpack(__half x, __half y) {
    return (uint32_t)__half_as_ushort(x) | ((uint32_t)__half_as_ushort(y) << 16);
}
__device__ __forceinline__ uint32_t pack2h(float2 v) {
    return hpack(__float2half_rn(v.x), __float2half_rn(v.y));
}

// ---------------- pack kernels (fragment-major) ----------------
__global__ void pack_A(const float* __restrict__ src, __half* __restrict__ dst,
                       int K, int nkcDst, int kcOff, int nunits)
{
    int u = blockIdx.x * 256 + threadIdx.x;
    if (u >= nunits) return;
    int lane = u & 31, mt = (u >> 5) & 7, ks = (u >> 8) & 1;
    int bk = u >> 9;
    int nkcSrc = K >> 5;
    int mtile = bk / nkcSrc, kchunk = bk - mtile * nkcSrc;
    int r0 = mtile * 128 + mt * 16 + (lane >> 2);
    int kb = kchunk * 32 + ks * 16 + (lane & 3) * 2;
    const float* s0 = src + (size_t)r0 * K + kb;
    const float* s1 = s0 + (size_t)8 * K;
    uint4 hi;
    hi.x = pack2h(*(const float2*)s0);
    hi.y = pack2h(*(const float2*)s1);
    hi.z = pack2h(*(const float2*)(s0 + 8));
    hi.w = pack2h(*(const float2*)(s1 + 8));
    size_t dblk = (size_t)mtile * nkcDst + kcOff + kchunk;
    int unit = (ks * 8 + mt) * 32 + lane;
    ((uint4*)(dst + dblk * 4096))[unit] = hi;
}

__global__ void pack_B(const float* __restrict__ src, __half* __restrict__ dst,
                       int K, int nkcDst, int nunits)
{
    int u = blockIdx.x * 256 + threadIdx.x;
    if (u >= nunits) return;
    int lane = u & 31, nt = (u >> 5) & 15, ks = (u >> 9) & 1;
    int bk = u >> 10;
    int nkcSrc = K >> 5;
    int ntile = bk / nkcSrc, kchunk = bk - ntile * nkcSrc;
    int n = ntile * 128 + nt * 8 + (lane >> 2);
    int kb = kchunk * 32 + ks * 16 + (lane & 3) * 2;
    const float* s = src + (size_t)n * K + kb;
    uint2 hi;
    hi.x = pack2h(*(const float2*)s);
    hi.y = pack2h(*(const float2*)(s + 8));
    size_t dblk = (size_t)ntile * nkcDst + kchunk;
    int unit = (ks * 16 + nt) * 32 + lane;
    ((uint2*)(dst + dblk * 4096))[unit] = hi;
}

// Wcat gate-interleaved: output row n' = 4*hc + gate; K = [w_ih|w_hh].
__global__ void pack_Bcat(const float* __restrict__ w_ih, const float* __restrict__ w_hh,
                          __half* __restrict__ dst, int nunits)
{
    int u = blockIdx.x * 256 + threadIdx.x;
    if (u >= nunits) return;
    int lane = u & 31, nt = (u >> 5) & 15, ks = (u >> 9) & 1;
    int bk = u >> 10;
    int ntile = bk >> 7, kchunk = bk & 127;
    int np = ntile * 128 + nt * 8 + (lane >> 2);
    int kb = kchunk * 32 + ks * 16 + (lane & 3) * 2;
    int gate = np & 3, hc = np >> 2;
    const float* base = (kb < HID) ? w_ih : w_hh;
    int kk = (kb < HID) ? kb : (kb - HID);
    const float* s = base + (size_t)(gate * HID + hc) * HID + kk;
    uint2 hi;
    hi.x = pack2h(*(const float2*)s);
    hi.y = pack2h(*(const float2*)(s + 8));
    size_t dblk = (size_t)ntile * 128 + kchunk;
    int unit = (ks * 16 + nt) * 32 + lane;
    ((uint2*)(dst + dblk * 4096))[unit] = hi;
}

// comm fused with A-pack: inp = e + alive_r*(S - alive_r*h)*inv -> dst kc [0,64)
__global__ void comm_pack_k(const float* __restrict__ e, const float* __restrict__ h,
                            const float* __restrict__ S, const float* __restrict__ alive,
                            const float* __restrict__ nal, int do_comm,
                            __half* __restrict__ dst)
{
    int u = blockIdx.x * 256 + threadIdx.x;   // 2048*2048/8 units
    int lane = u & 31, mt = (u >> 5) & 7, ks = (u >> 8) & 1;
    int bk = u >> 9;
    int mtile = bk >> 6, kchunk = bk & 63;    // source nkc = 64
    int r0 = mtile * 128 + mt * 16 + (lane >> 2);
    int kb = kchunk * 32 + ks * 16 + (lane & 3) * 2;
    float inv = do_comm ? 1.0f / (*nal - 1.0f) : 0.0f;
    float a0 = alive[r0], a1 = alive[r0 + 8];
    float2 Sv0 = *(const float2*)(S + kb);
    float2 Sv1 = *(const float2*)(S + kb + 8);
    const float* e0 = e + (size_t)r0 * HID + kb;
    const float* h0 = h + (size_t)r0 * HID + kb;
    float2 e00 = *(const float2*)e0;
    float2 e10 = *(const float2*)(e0 + (size_t)8 * HID);
    float2 e01 = *(const float2*)(e0 + 8);
    float2 e11 = *(const float2*)(e0 + (size_t)8 * HID + 8);
    float2 h00 = *(const float2*)h0;
    float2 h10 = *(const float2*)(h0 + (size_t)8 * HID);
    float2 h01 = *(const float2*)(h0 + 8);
    float2 h11 = *(const float2*)(h0 + (size_t)8 * HID + 8);
    float2 p0 = { e00.x + a0 * (Sv0.x - a0 * h00.x) * inv,
                  e00.y + a0 * (Sv0.y - a0 * h00.y) * inv };
    float2 p1 = { e10.x + a1 * (Sv0.x - a1 * h10.x) * inv,
                  e10.y + a1 * (Sv0.y - a1 * h10.y) * inv };
    float2 p2 = { e01.x + a0 * (Sv1.x - a0 * h01.x) * inv,
                  e01.y + a0 * (Sv1.y - a0 * h01.y) * inv };
    float2 p3 = { e11.x + a1 * (Sv1.x - a1 * h11.x) * inv,
                  e11.y + a1 * (Sv1.y - a1 * h11.y) * inv };
    uint4 hi;
    hi.x = pack2h(p0); hi.y = pack2h(p1);
    hi.z = pack2h(p2); hi.w = pack2h(p3);
    size_t dblk = (size_t)mtile * 128 + kchunk;
    int unit = (ks * 8 + mt) * 32 + lane;
    ((uint4*)(dst + dblk * 4096))[unit] = hi;
}

// ---------------- GEMM: C(128x128) = A*B^T, fp16, 5-stage BK=32 pipeline ----------
// EPI=1: bias+tanh -> C.  EPI=2: gate-interleaved LSTM epilogue; packs h into
// packDst (the OTHER Apack buffer) at kc = 64 + NT. One N-tile = 32 hidden cols
// = exactly one pack block.
template<int EPI>
__global__ void __launch_bounds__(128, 2)
gemm_fused(const __half* __restrict__ Ap, const __half* __restrict__ Bp,
           const float* __restrict__ bias, float* __restrict__ C,
           int nkcA, int nkcB, int kcCount, int ldc,
           float* __restrict__ cell, float* __restrict__ hout,
           __half* __restrict__ packDst, int dopack)
{
    extern __shared__ __align__(16) char smem[];
    const uint32_t sb = smem_u32(smem);
    const int tid = threadIdx.x;
    const int MT = blockIdx.y, NT = blockIdx.x;
    const int wid = tid >> 5, lane = tid & 31;
    const int wm = wid >> 1, wn = wid & 1;

    float acc[4][8][4];
#pragma unroll
    for (int i = 0; i < 4; i++)
#pragma unroll
        for (int j = 0; j < 8; j++)
#pragma unroll
            for (int t = 0; t < 4; t++) acc[i][j][t] = 0.0f;

    auto issue = [&](int c) {
        const char* ab = (const char*)Ap + ((size_t)MT * nkcA + c) * 8192;
        const char* bb = (const char*)Bp + ((size_t)NT * nkcB + c) * 8192;
        uint32_t d = sb + (uint32_t)(c % NSTG) * STAGE_B;
#pragma unroll
        for (int i = 0; i < 4; i++) {
            uint32_t o = i * 2048 + tid * 16;
            cpasync16(d + o,        ab + o);   // A
            cpasync16(d + 8192 + o, bb + o);   // B
        }
        asm volatile("cp.async.commit_group;");
    };

    issue(0); issue(1); issue(2); issue(3);

    for (int vk = 0; vk < kcCount; vk++) {
        if (vk + 3 < kcCount)      asm volatile("cp.async.wait_group 3;");
        else if (vk + 2 < kcCount) asm volatile("cp.async.wait_group 2;");
        else if (vk + 1 < kcCount) asm volatile("cp.async.wait_group 1;");
        else                       asm volatile("cp.async.wait_group 0;");
        __syncthreads();
        if (vk + 4 < kcCount) issue(vk + 4);

        uint32_t st = sb + (uint32_t)(vk % NSTG) * STAGE_B;
#pragma unroll
        for (int ks = 0; ks < 2; ks++) {
            uint32_t a[4][4], b[8][2];
#pragma unroll
            for (int j = 0; j < 8; j++) {
                uint2 v = lds64(st + 8192u + (uint32_t)((ks * 16 + wn * 8 + j) * 256 + lane * 8));
                b[j][0] = v.x; b[j][1] = v.y;
            }
#pragma unroll
            for (int i = 0; i < 4; i++) {
                uint4 v = lds128(st + (uint32_t)((ks * 8 + wm * 4 + i) * 512 + lane * 16));
                a[i][0] = v.x; a[i][1] = v.y; a[i][2] = v.z; a[i][3] = v.w;
            }
#pragma unroll
            for (int i = 0; i < 4; i++)
#pragma unroll
                for (int j = 0; j < 8; j++) mma16816(acc[i][j], a[i], b[j]);
        }
    }

    if (EPI == 1) {
        const int rowb = MT * 128 + wm * 64;
        const int colb = NT * 128 + wn * 64;
#pragma unroll
        for (int i = 0; i < 4; i++) {
            int r0 = rowb + i * 16 + (lane >> 2);
#pragma unroll
            for (int j = 0; j < 8; j++) {
                int c0 = colb + j * 8 + (lane & 3) * 2;
                float b0 = bias[c0], b1 = bias[c0 + 1];
                float2 v0 = { tanhf(acc[i][j][0] + b0), tanhf(acc[i][j][1] + b1) };
                float2 v1 = { tanhf(acc[i][j][2] + b0), tanhf(acc[i][j][3] + b1) };
                *(float2*)(C + (size_t)r0 * ldc + c0) = v0;
                *(float2*)(C + (size_t)(r0 + 8) * ldc + c0) = v1;
            }
        }
    } else {
        // ---- fused LSTM epilogue (writes h-pack into the OTHER buffer) ----
        __syncthreads();                       // stage mem free after mainloop
        float* zbuf = (float*)smem;            // [128][132]
        const int colT = NT * 128;
#pragma unroll
        for (int i = 0; i < 4; i++) {
            int rr = wm * 64 + i * 16 + (lane >> 2);
#pragma unroll
            for (int j = 0; j < 8; j++) {
                int cc = wn * 64 + j * 8 + (lane & 3) * 2;
                float b0 = bias[colT + cc], b1 = bias[colT + cc + 1];
                float2 v0 = { acc[i][j][0] + b0, acc[i][j][1] + b1 };
                float2 v1 = { acc[i][j][2] + b0, acc[i][j][3] + b1 };
                *(float2*)&zbuf[rr * 132 + cc] = v0;
                *(float2*)&zbuf[(rr + 8) * 132 + cc] = v1;
            }
        }
        __syncthreads();
        float* sh = (float*)(smem + 67584);    // [128][33]
        const int r = MT * 128 + tid;
        float* crow = cell + (size_t)r * HID + NT * 32;
        float* hrow = hout + (size_t)r * HID + NT * 32;
#pragma unroll
        for (int c4 = 0; c4 < 8; c4++) {
            float4 za = *(float4*)&zbuf[tid * 132 + c4 * 16 + 0];   // (i,f,g,o)
            float4 zb = *(float4*)&zbuf[tid * 132 + c4 * 16 + 4];
            float4 zc = *(float4*)&zbuf[tid * 132 + c4 * 16 + 8];
            float4 zd = *(float4*)&zbuf[tid * 132 + c4 * 16 + 12];
            float4 cold = *(const float4*)(crow + c4 * 4);
            float4 cn, hv;
            cn.x = sigf(za.y) * cold.x + sigf(za.x) * tanhf(za.z);
            cn.y = sigf(zb.y) * cold.y + sigf(zb.x) * tanhf(zb.z);
            cn.z = sigf(zc.y) * cold.z + sigf(zc.x) * tanhf(zc.z);
            cn.w = sigf(zd.y) * cold.w + sigf(zd.x) * tanhf(zd.z);
            hv.x = sigf(za.w) * tanhf(cn.x);
            hv.y = sigf(zb.w) * tanhf(cn.y);
            hv.z = sigf(zc.w) * tanhf(cn.z);
            hv.w = sigf(zd.w) * tanhf(cn.w);
            *(float4*)(crow + c4 * 4) = cn;
            *(float4*)(hrow + c4 * 4) = hv;
            sh[tid * 33 + c4 * 4 + 0] = hv.x;
            sh[tid * 33 + c4 * 4 + 1] = hv.y;
            sh[tid * 33 + c4 * 4 + 2] = hv.z;
            sh[tid * 33 + c4 * 4 + 3] = hv.w;
        }
        if (dopack) {
            __syncthreads();
            __half* dblk = packDst + ((size_t)MT * 128 + 64 + NT) * 4096;
#pragma unroll
            for (int t = 0; t < 4; t++) {
                int uu = tid + t * 128;
                int ll = uu & 31, mt2 = (uu >> 5) & 7, ks2 = uu >> 8;
                int R = mt2 * 16 + (ll >> 2), K0 = ks2 * 16 + (ll & 3) * 2;
                uint4 hi;
                hi.x = pack2h({ sh[R * 33 + K0],           sh[R * 33 + K0 + 1] });
                hi.y = pack2h({ sh[(R + 8) * 33 + K0],     sh[(R + 8) * 33 + K0 + 1] });
                hi.z = pack2h({ sh[R * 33 + K0 + 8],       sh[R * 33 + K0 + 9] });
                hi.w = pack2h({ sh[(R + 8) * 33 + K0 + 8], sh[(R + 8) * 33 + K0 + 9] });
                ((uint4*)dblk)[uu] = hi;
            }
        }
    }
}

// ---------------- column sums for comm ----------------
__global__ void colsum_part_k(const float* __restrict__ h, const float* __restrict__ alive,
                              float* __restrict__ part)
{
    int col = blockIdx.x * 128 + threadIdx.x;
    int r0 = blockIdx.y * 128;
    float s = 0.0f;
    for (int r = r0; r < r0 + 128; r++)
        s = fmaf(alive[r], h[(size_t)r * HID + col], s);
    part[blockIdx.y * HID + col] = s;
}
__global__ void colsum_red_k(const float* __restrict__ part, float* __restrict__ S)
{
    int c = blockIdx.x * 256 + threadIdx.x;
    float s = 0.0f;
#pragma unroll
    for (int i = 0; i < 16; i++) s += part[i * HID + c];
    S[c] = s;
}

// ---------------- misc ----------------
__global__ void nalive_k(const float* __restrict__ alive, float* __restrict__ out, int n)
{
    __shared__ float s[256];
    float v = 0.0f;
    for (int i = threadIdx.x; i < n; i += 256) v += alive[i];
    s[threadIdx.x] = v;
    __syncthreads();
    for (int st = 128; st > 0; st >>= 1) {
        if (threadIdx.x < st) s[threadIdx.x] += s[threadIdx.x + st];
        __syncthreads();
    }
    if (threadIdx.x == 0) *out = s[0];
}
// permuted bias: o[4*hc+g] = b_ih[g*HID+hc] + b_hh[g*HID+hc]
__global__ void bias_perm_k(const float* __restrict__ a, const float* __restrict__ b,
                            float* __restrict__ o, int n)
{
    int i = blockIdx.x * blockDim.x + threadIdx.x;
    if (i < n) {
        int g = i & 3, hc = i >> 2;
        o[i] = a[g * HID + hc] + b[g * HID + hc];
    }
}

// ---------------- head ----------------
__global__ void __launch_bounds__(256)
head_k(const float* __restrict__ h,
       const float* __restrict__ act_w, const float* __restrict__ act_b,
       const float* __restrict__ val_w, const float* __restrict__ val_b,
       float* __restrict__ out)
{
    const int n = blockIdx.x;
    const int tid = threadIdx.x;
    __shared__ float sh[HID];
    __shared__ float partial[4][ACT_D];
    __shared__ float vred[256];
    __shared__ float logits[ACT_D];

    const float* hr = h + (size_t)n * HID;
    for (int k = tid; k < HID; k += 256) sh[k] = hr[k];
    __syncthreads();

    const int col = tid & 63;
    const int part = tid >> 6;
    const float* w = act_w + (size_t)col * HID;
    float s = 0.0f;
    const int kbeg = part * (HID / 4);
    for (int k = kbeg; k < kbeg + HID / 4; k++) s = fmaf(sh[k], w[k], s);
    partial[part][col] = s;

    float v = 0.0f;
    for (int k = tid; k < HID; k += 256) v = fmaf(sh[k], val_w[k], v);
    vred[tid] = v;
    __syncthreads();

    if (tid < ACT_D)
        logits[tid] = partial[0][tid] + partial[1][tid] + partial[2][tid]
                    + partial[3][tid] + act_b[tid];

    for (int st = 128; st > 0; st >>= 1) {
        if (tid < st) vred[tid] += vred[tid + st];
        __syncthreads();
    }
    if (tid == 0) out[(size_t)NN_AG * ACT_D + n] = vred[0] + val_b[0];

    if (tid < 32) {
        float a = logits[tid], b = logits[tid + 32];
        float m = fmaxf(a, b);
#pragma unroll
        for (int o = 16; o > 0; o >>= 1) m = fmaxf(m, __shfl_xor_sync(0xffffffffu, m, o));
        float se = expf(a - m) + expf(b - m);
#pragma unroll
        for (int o = 16; o > 0; o >>= 1) se += __shfl_xor_sync(0xffffffffu, se, o);
        float lse = m + logf(se);
        out[(size_t)n * ACT_D + tid]      = a - lse;
        out[(size_t)n * ACT_D + tid + 32] = b - lse;
    }
}

// ---------------- launcher ----------------
extern "C" void kernel_launch(void* const* d_in, const int* in_sizes, int n_in,
                              void* d_out, int out_size)
{
    const float* obs    = (const float*)d_in[0];
    const float* alive  = (const float*)d_in[1];
    const float* enc_w  = (const float*)d_in[2];
    const float* enc_b  = (const float*)d_in[3];
    // d_in[4], d_in[5]: g_w, g_b — gate == 1 always (ceil(sigmoid), |logit| << 104)
    const float* w_ih   = (const float*)d_in[6];
    const float* w_hh   = (const float*)d_in[7];
    const float* b_ih   = (const float*)d_in[8];
    const float* b_hh   = (const float*)d_in[9];
    const float* act_w  = (const float*)d_in[10];
    const float* act_b  = (const float*)d_in[11];
    const float* val_w  = (const float*)d_in[12];
    const float* val_b  = (const float*)d_in[13];
    float* out = (float*)d_out;

    float *e, *h, *cell, *part, *S, *bsum, *nal;
    __half *ApA, *ApB, *Aobs, *Wcat, *Wenc;
    cudaGetSymbolAddress((void**)&e,    g_e);
    cudaGetSymbolAddress((void**)&h,    g_h);
    cudaGetSymbolAddress((void**)&cell, g_cell);
    cudaGetSymbolAddress((void**)&part, g_part);
    cudaGetSymbolAddress((void**)&S,    g_S);
    cudaGetSymbolAddress((void**)&bsum, g_bsum);
    cudaGetSymbolAddress((void**)&nal,  g_nalive);
    cudaGetSymbolAddress((void**)&ApA,  g_ApackA);
    cudaGetSymbolAddress((void**)&ApB,  g_ApackB);
    cudaGetSymbolAddress((void**)&Aobs, g_Aobs);
    cudaGetSymbolAddress((void**)&Wcat, g_Wcat);
    cudaGetSymbolAddress((void**)&Wenc, g_Wenc);

    cudaFuncSetAttribute(gemm_fused<1>, cudaFuncAttributeMaxDynamicSharedMemorySize, SMEM_DYN);
    cudaFuncSetAttribute(gemm_fused<2>, cudaFuncAttributeMaxDynamicSharedMemorySize, SMEM_DYN);

    const size_t NH = (size_t)NN_AG * HID;
    cudaMemsetAsync(h,    0, NH * sizeof(float));
    cudaMemsetAsync(cell, 0, NH * sizeof(float));

    // packs first so the encoder GEMM lands in ncu's profiled slot (skip-5)
    {
        int unitsAobs = NN_AG * OBS_D / 8;
        pack_A<<<(unitsAobs + 255) / 256, 256>>>(obs, Aobs, OBS_D, 32, 0, unitsAobs);
        int unitsWenc = HID * OBS_D / 4;
        pack_B<<<(unitsWenc + 255) / 256, 256>>>(enc_w, Wenc, OBS_D, 32, unitsWenc);
        int unitsWcat = (4 * HID) * (2 * HID) / 4;
        pack_Bcat<<<(unitsWcat + 255) / 256, 256>>>(w_ih, w_hh, Wcat, unitsWcat);
    }

    // encoder: e = tanh(obs @ enc_w^T + enc_b)
    {
        dim3 grid(HID / 128, NN_AG / 128);
        gemm_fused<1><<<grid, 128, SMEM_DYN>>>(Aobs, Wenc, enc_b, e, 32, 32, 32, HID,
                                               nullptr, nullptr, nullptr, 0);
    }

    nalive_k<<<1, 256>>>(alive, nal, NN_AG);
    bias_perm_k<<<(4 * HID + 255) / 256, 256>>>(b_ih, b_hh, bsum, 4 * HID);

    const dim3 gridZ(4 * HID / 128, NN_AG / 128);   // 64 x 16
    const dim3 gridCS(HID / 128, 16);
    const int unitsNH = (int)(NH / 8);

    __half* Abuf[2] = { ApA, ApB };
    for (int it = 0; it < ITERS; it++) {
        __half* cur = Abuf[it & 1];
        __half* nxt = Abuf[(it + 1) & 1];
        if (it > 0) {
            colsum_part_k<<<gridCS, 128>>>(h, alive, part);
            colsum_red_k<<<HID / 256, 256>>>(part, S);
        }
        comm_pack_k<<<(unitsNH + 255) / 256, 256>>>(e, h, S, alive, nal,
                                                    it > 0 ? 1 : 0, cur);
        // z = [inp|h] @ Wcat^T + bsum with fused LSTM; h-pack -> OTHER buffer
        gemm_fused<2><<<gridZ, 128, SMEM_DYN>>>(cur, Wcat, bsum, nullptr,
                                                128, 128, (it > 0) ? 128 : 64, 0,
                                                cell, h, nxt,
                                                (it < ITERS - 1) ? 1 : 0);
    }

    head_k<<<NN_AG, 256>>>(h, act_w, act_b, val_w, val_b, out);
}

// round 15
// speedup vs baseline: 1.1582x; 1.1582x over previous
#include <cuda_runtime.h>
#include <cuda_fp16.h>
#include <math.h>
#include <stdint.h>

// ---------------- problem constants ----------------
#define NN_AG 2048
#define HID   2048
#define OBS_D 1024
#define ACT_D 64
#define ITERS 3

// ---------------- device scratch ----------------
// fragment-major packed fp16; one 8KB block = 128 rows x 32 k
__device__ __align__(16) __half g_Hp0 [(size_t)16 * 64 * 4096];   // h pack, buffer 0
__device__ __align__(16) __half g_Hp1 [(size_t)16 * 64 * 4096];   // h pack, buffer 1
__device__ __align__(16) __half g_Epk [(size_t)16 * 64 * 4096];   // e pack
__device__ __align__(16) __half g_Aobs[(size_t)16 * 32 * 4096];   // obs
__device__ __align__(16) __half g_Wc  [(size_t)64 * 64 * 4096];   // gate-perm (w_hh - inv*w_ih)
__device__ __align__(16) __half g_Wip [(size_t)64 * 64 * 4096];   // gate-perm w_ih
__device__ __align__(16) __half g_Wenc[(size_t)16 * 32 * 4096];   // enc_w
__device__ float g_e   [(size_t)NN_AG * HID];
__device__ float g_ze  [(size_t)NN_AG * 4 * HID];   // e@W_ih^T + bias (gate-perm cols)
__device__ float g_h   [(size_t)NN_AG * HID];
__device__ float g_cell[(size_t)NN_AG * HID];
__device__ float g_part[16 * HID];
__device__ float g_S   [HID];
__device__ float g_u   [4 * HID];                   // W_ih @ S (gate-perm)
__device__ float g_bsum[4 * HID];
__device__ float g_nalive;

#define STAGE_B 16384          // [A 8K][B 8K], BK=32
#define NSTG 5
#define SMEM_DYN 84480         // epilogue: zbuf 67584 + sh 16896

__device__ __forceinline__ float sigf(float x) { return 1.0f / (1.0f + expf(-x)); }

// ---------------- low-level helpers ----------------
__device__ __forceinline__ uint32_t smem_u32(const void* p) {
    uint32_t a;
    asm("{ .reg .u64 t; cvta.to.shared.u64 t, %1; cvt.u32.u64 %0, t; }" : "=r"(a) : "l"(p));
    return a;
}
__device__ __forceinline__ void cpasync16(uint32_t d, const void* s) {
    asm volatile("cp.async.cg.shared.global [%0], [%1], 16;" :: "r"(d), "l"(s));
}
__device__ __forceinline__ uint4 lds128(uint32_t a) {
    uint4 v;
    asm volatile("ld.shared.v4.b32 {%0,%1,%2,%3}, [%4];"
                 : "=r"(v.x), "=r"(v.y), "=r"(v.z), "=r"(v.w) : "r"(a));
    return v;
}
__device__ __forceinline__ uint2 lds64(uint32_t a) {
    uint2 v;
    asm volatile("ld.shared.v2.b32 {%0,%1}, [%2];" : "=r"(v.x), "=r"(v.y) : "r"(a));
    return v;
}
__device__ __forceinline__ void mma16816(float* c, const uint32_t* a, const uint32_t* b) {
    asm volatile(
        "mma.sync.aligned.m16n8k16.row.col.f32.f16.f16.f32 "
        "{%0,%1,%2,%3}, {%4,%5,%6,%7}, {%8,%9}, {%0,%1,%2,%3};"
        : "+f"(c[0]), "+f"(c[1]), "+f"(c[2]), "+f"(c[3])
        : "r"(a[0]), "r"(a[1]), "r"(a[2]), "r"(a[3]), "r"(b[0]), "r"(b[1]));
}
__device__ __forceinline__ uint32_t hpack(__half x, __half y) {
    return (uint32_t)__half_as_ushort(x) | ((uint32_t)__half_as_ushort(y) << 16);
}
__device__ __forceinline__ uint32_t pack2h(float2 v) {
    return hpack(__float2half_rn(v.x), __float2half_rn(v.y));
}

// ---------------- pack kernels (fragment-major) ----------------
// A block: unit u16B; rows mt*16+(lane/4)(+8), k = ks*16+(lane%4)*2 (+8). 8 elems/unit.
__global__ void pack_A(const float* __restrict__ src, __half* __restrict__ dst,
                       int K, int nkcDst, int nunits)
{
    int u = blockIdx.x * 256 + threadIdx.x;
    if (u >= nunits) return;
    int lane = u & 31, mt = (u >> 5) & 7, ks = (u >> 8) & 1;
    int bk = u >> 9;
    int nkcSrc = K >> 5;
    int mtile = bk / nkcSrc, kchunk = bk - mtile * nkcSrc;
    int r0 = mtile * 128 + mt * 16 + (lane >> 2);
    int kb = kchunk * 32 + ks * 16 + (lane & 3) * 2;
    const float* s0 = src + (size_t)r0 * K + kb;
    const float* s1 = s0 + (size_t)8 * K;
    uint4 hi;
    hi.x = pack2h(*(const float2*)s0);
    hi.y = pack2h(*(const float2*)s1);
    hi.z = pack2h(*(const float2*)(s0 + 8));
    hi.w = pack2h(*(const float2*)(s1 + 8));
    size_t dblk = (size_t)mtile * nkcDst + kchunk;
    int unit = (ks * 8 + mt) * 32 + lane;
    ((uint4*)(dst + dblk * 4096))[unit] = hi;
}

// plain B pack (enc_w): n = nt*8+(lane/4), k = ks*16+(lane%4)*2 (+8). 4 elems/unit.
__global__ void pack_B(const float* __restrict__ src, __half* __restrict__ dst,
                       int K, int nkcDst, int nunits)
{
    int u = blockIdx.x * 256 + threadIdx.x;
    if (u >= nunits) return;
    int lane = u & 31, nt = (u >> 5) & 15, ks = (u >> 9) & 1;
    int bk = u >> 10;
    int nkcSrc = K >> 5;
    int ntile = bk / nkcSrc, kchunk = bk - ntile * nkcSrc;
    int n = ntile * 128 + nt * 8 + (lane >> 2);
    int kb = kchunk * 32 + ks * 16 + (lane & 3) * 2;
    const float* s = src + (size_t)n * K + kb;
    uint2 hi;
    hi.x = pack2h(*(const float2*)s);
    hi.y = pack2h(*(const float2*)(s + 8));
    size_t dblk = (size_t)ntile * nkcDst + kchunk;
    int unit = (ks * 16 + nt) * 32 + lane;
    ((uint2*)(dst + dblk * 4096))[unit] = hi;
}

// gate-interleaved B pack over K=HID: out row n' = 4*hc+gate; value = wA + sc*wB
// (sc = -1/(nal-1) when nal given, else 0). nkc = 64.
__global__ void pack_Bg(const float* __restrict__ wA, const float* __restrict__ wB,
                        const float* __restrict__ nal, __half* __restrict__ dst,
                        int nunits)
{
    int u = blockIdx.x * 256 + threadIdx.x;
    if (u >= nunits) return;
    int lane = u & 31, nt = (u >> 5) & 15, ks = (u >> 9) & 1;
    int bk = u >> 10;
    int ntile = bk >> 6, kchunk = bk & 63;
    int np = ntile * 128 + nt * 8 + (lane >> 2);
    int kb = kchunk * 32 + ks * 16 + (lane & 3) * 2;
    int gate = np & 3, hc = np >> 2;
    float sc = nal ? (-1.0f / (*nal - 1.0f)) : 0.0f;
    size_t off = (size_t)(gate * HID + hc) * HID + kb;
    float2 a0 = *(const float2*)(wA + off);
    float2 a1 = *(const float2*)(wA + off + 8);
    float2 b0 = *(const float2*)(wB + off);
    float2 b1 = *(const float2*)(wB + off + 8);
    float2 v0 = { a0.x + sc * b0.x, a0.y + sc * b0.y };
    float2 v1 = { a1.x + sc * b1.x, a1.y + sc * b1.y };
    uint2 hi;
    hi.x = pack2h(v0);
    hi.y = pack2h(v1);
    size_t dblk = (size_t)ntile * 64 + kchunk;
    int unit = (ks * 16 + nt) * 32 + lane;
    ((uint2*)(dst + dblk * 4096))[unit] = hi;
}

// ---------------- iter-0 LSTM: cell=sig(zi)tanh(zg), h=sig(zo)tanh(cell); pack h ----
__global__ void lstm0_pack_k(const float* __restrict__ ze, float* __restrict__ cell,
                             float* __restrict__ h, __half* __restrict__ dst)
{
    int u = blockIdx.x * 256 + threadIdx.x;   // NH/8 units
    int lane = u & 31, mt = (u >> 5) & 7, ks = (u >> 8) & 1;
    int bk = u >> 9;
    int mtile = bk >> 6, kchunk = bk & 63;
    int r0 = mtile * 128 + mt * 16 + (lane >> 2);
    int kb = kchunk * 32 + ks * 16 + (lane & 3) * 2;

    auto do2 = [&](int r, int hc) -> uint32_t {
        const float* zr = ze + (size_t)r * (4 * HID) + 4 * hc;
        float4 z0 = *(const float4*)zr;        // (i,f,g,o) for hc
        float4 z1 = *(const float4*)(zr + 4);  // for hc+1
        float c0 = sigf(z0.x) * tanhf(z0.z);
        float c1 = sigf(z1.x) * tanhf(z1.z);
        float h0 = sigf(z0.w) * tanhf(c0);
        float h1 = sigf(z1.w) * tanhf(c1);
        *(float2*)(cell + (size_t)r * HID + hc) = { c0, c1 };
        *(float2*)(h    + (size_t)r * HID + hc) = { h0, h1 };
        return pack2h({ h0, h1 });
    };
    uint4 hi;
    hi.x = do2(r0,     kb);
    hi.y = do2(r0 + 8, kb);
    hi.z = do2(r0,     kb + 8);
    hi.w = do2(r0 + 8, kb + 8);
    size_t dblk = (size_t)mtile * 64 + kchunk;
    int unit = (ks * 8 + mt) * 32 + lane;
    ((uint4*)(dst + dblk * 4096))[unit] = hi;
}

// ---------------- GEMV: u[n'] = dot(w_ih[gate*HID+hc], S), permuted n' ----------
__global__ void gemv_u_k(const float* __restrict__ w_ih, const float* __restrict__ S,
                         float* __restrict__ gu)
{
    int wrp = (blockIdx.x * 256 + threadIdx.x) >> 5;
    int lane = threadIdx.x & 31;
    if (wrp >= 4 * HID) return;
    int gate = wrp & 3, hc = wrp >> 2;
    const float4* row = (const float4*)(w_ih + (size_t)(gate * HID + hc) * HID);
    const float4* Sv = (const float4*)S;
    float s = 0.0f;
    for (int k = lane; k < HID / 4; k += 32) {
        float4 a = row[k], b = Sv[k];
        s += a.x * b.x + a.y * b.y + a.z * b.z + a.w * b.w;
    }
#pragma unroll
    for (int o = 16; o > 0; o >>= 1) s += __shfl_xor_sync(0xffffffffu, s, o);
    if (lane == 0) gu[wrp] = s;
}

// ---------------- GEMM: C(128x128) = A*B^T, fp16, 5-stage BK=32 pipeline ----------
// EPI=1: bias+tanh -> C (encoder).  EPI=3: bias -> C (ze).
// EPI=2: z = acc + ze + inv*u, fused LSTM, pack h -> packDst block (MT*64+NT).
template<int EPI>
__global__ void __launch_bounds__(128, 2)
gemm_fused(const __half* __restrict__ Ap, const __half* __restrict__ Bp,
           const float* __restrict__ bias, float* __restrict__ C,
           int nkcA, int nkcB, int kcCount, int ldc,
           const float* __restrict__ ze, const float* __restrict__ gu,
           const float* __restrict__ nal,
           float* __restrict__ cell, float* __restrict__ hout,
           __half* __restrict__ packDst, int dopack)
{
    extern __shared__ __align__(16) char smem[];
    const uint32_t sb = smem_u32(smem);
    const int tid = threadIdx.x;
    const int MT = blockIdx.y, NT = blockIdx.x;
    const int wid = tid >> 5, lane = tid & 31;
    const int wm = wid >> 1, wn = wid & 1;

    float acc[4][8][4];
#pragma unroll
    for (int i = 0; i < 4; i++)
#pragma unroll
        for (int j = 0; j < 8; j++)
#pragma unroll
            for (int t = 0; t < 4; t++) acc[i][j][t] = 0.0f;

    auto issue = [&](int c) {
        const char* ab = (const char*)Ap + ((size_t)MT * nkcA + c) * 8192;
        const char* bb = (const char*)Bp + ((size_t)NT * nkcB + c) * 8192;
        uint32_t d = sb + (uint32_t)(c % NSTG) * STAGE_B;
#pragma unroll
        for (int i = 0; i < 4; i++) {
            uint32_t o = i * 2048 + tid * 16;
            cpasync16(d + o,        ab + o);   // A
            cpasync16(d + 8192 + o, bb + o);   // B
        }
        asm volatile("cp.async.commit_group;");
    };

    issue(0); issue(1); issue(2); issue(3);

    for (int vk = 0; vk < kcCount; vk++) {
        if (vk + 3 < kcCount)      asm volatile("cp.async.wait_group 3;");
        else if (vk + 2 < kcCount) asm volatile("cp.async.wait_group 2;");
        else if (vk + 1 < kcCount) asm volatile("cp.async.wait_group 1;");
        else                       asm volatile("cp.async.wait_group 0;");
        __syncthreads();
        if (vk + 4 < kcCount) issue(vk + 4);

        uint32_t st = sb + (uint32_t)(vk % NSTG) * STAGE_B;
#pragma unroll
        for (int ks = 0; ks < 2; ks++) {
            uint32_t a[4][4], b[8][2];
#pragma unroll
            for (int j = 0; j < 8; j++) {
                uint2 v = lds64(st + 8192u + (uint32_t)((ks * 16 + wn * 8 + j) * 256 + lane * 8));
                b[j][0] = v.x; b[j][1] = v.y;
            }
#pragma unroll
            for (int i = 0; i < 4; i++) {
                uint4 v = lds128(st + (uint32_t)((ks * 8 + wm * 4 + i) * 512 + lane * 16));
                a[i][0] = v.x; a[i][1] = v.y; a[i][2] = v.z; a[i][3] = v.w;
            }
#pragma unroll
            for (int i = 0; i < 4; i++)
#pragma unroll
                for (int j = 0; j < 8; j++) mma16816(acc[i][j], a[i], b[j]);
        }
    }

    if (EPI == 1 || EPI == 3) {
        const int rowb = MT * 128 + wm * 64;
        const int colb = NT * 128 + wn * 64;
#pragma unroll
        for (int i = 0; i < 4; i++) {
            int r0 = rowb + i * 16 + (lane >> 2);
#pragma unroll
            for (int j = 0; j < 8; j++) {
                int c0 = colb + j * 8 + (lane & 3) * 2;
                float b0 = bias[c0], b1 = bias[c0 + 1];
                float x0 = acc[i][j][0] + b0, x1 = acc[i][j][1] + b1;
                float x2 = acc[i][j][2] + b0, x3 = acc[i][j][3] + b1;
                if (EPI == 1) { x0 = tanhf(x0); x1 = tanhf(x1); x2 = tanhf(x2); x3 = tanhf(x3); }
                float2 v0 = {x0, x1}, v1 = {x2, x3};
                *(float2*)(C + (size_t)r0 * ldc + c0) = v0;
                *(float2*)(C + (size_t)(r0 + 8) * ldc + c0) = v1;
            }
        }
    } else {
        // ---- fused LSTM epilogue: z = acc + ze + inv*u ----
        __syncthreads();
        float* zbuf = (float*)smem;            // [128][132]
        const int colT = NT * 128;
        const float inv = 1.0f / (*nal - 1.0f);
#pragma unroll
        for (int i = 0; i < 4; i++) {
            int rr = wm * 64 + i * 16 + (lane >> 2);
            int gr = MT * 128 + rr;
#pragma unroll
            for (int j = 0; j < 8; j++) {
                int cc = wn * 64 + j * 8 + (lane & 3) * 2;
                const float* zer = ze + (size_t)gr * (4 * HID) + colT + cc;
                float2 ze0 = *(const float2*)zer;
                float2 ze1 = *(const float2*)(zer + (size_t)8 * (4 * HID));
                float u0 = inv * gu[colT + cc], u1 = inv * gu[colT + cc + 1];
                float2 v0 = { acc[i][j][0] + ze0.x + u0, acc[i][j][1] + ze0.y + u1 };
                float2 v1 = { acc[i][j][2] + ze1.x + u0, acc[i][j][3] + ze1.y + u1 };
                *(float2*)&zbuf[rr * 132 + cc] = v0;
                *(float2*)&zbuf[(rr + 8) * 132 + cc] = v1;
            }
        }
        __syncthreads();
        float* sh = (float*)(smem + 67584);    // [128][33]
        const int r = MT * 128 + tid;
        float* crow = cell + (size_t)r * HID + NT * 32;
        float* hrow = hout + (size_t)r * HID + NT * 32;
#pragma unroll
        for (int c4 = 0; c4 < 8; c4++) {
            float4 za = *(float4*)&zbuf[tid * 132 + c4 * 16 + 0];   // (i,f,g,o)
            float4 zb = *(float4*)&zbuf[tid * 132 + c4 * 16 + 4];
            float4 zc = *(float4*)&zbuf[tid * 132 + c4 * 16 + 8];
            float4 zd = *(float4*)&zbuf[tid * 132 + c4 * 16 + 12];
            float4 cold = *(const float4*)(crow + c4 * 4);
            float4 cn, hv;
            cn.x = sigf(za.y) * cold.x + sigf(za.x) * tanhf(za.z);
            cn.y = sigf(zb.y) * cold.y + sigf(zb.x) * tanhf(zb.z);
            cn.z = sigf(zc.y) * cold.z + sigf(zc.x) * tanhf(zc.z);
            cn.w = sigf(zd.y) * cold.w + sigf(zd.x) * tanhf(zd.z);
            hv.x = sigf(za.w) * tanhf(cn.x);
            hv.y = sigf(zb.w) * tanhf(cn.y);
            hv.z = sigf(zc.w) * tanhf(cn.z);
            hv.w = sigf(zd.w) * tanhf(cn.w);
            *(float4*)(crow + c4 * 4) = cn;
            *(float4*)(hrow + c4 * 4) = hv;
            sh[tid * 33 + c4 * 4 + 0] = hv.x;
            sh[tid * 33 + c4 * 4 + 1] = hv.y;
            sh[tid * 33 + c4 * 4 + 2] = hv.z;
            sh[tid * 33 + c4 * 4 + 3] = hv.w;
        }
        if (dopack) {
            __syncthreads();
            __half* dblk = packDst + ((size_t)MT * 64 + NT) * 4096;
#pragma unroll
            for (int t = 0; t < 4; t++) {
                int uu = tid + t * 128;
                int ll = uu & 31, mt2 = (uu >> 5) & 7, ks2 = uu >> 8;
                int R = mt2 * 16 + (ll >> 2), K0 = ks2 * 16 + (ll & 3) * 2;
                uint4 hi;
                hi.x = pack2h({ sh[R * 33 + K0],           sh[R * 33 + K0 + 1] });
                hi.y = pack2h({ sh[(R + 8) * 33 + K0],     sh[(R + 8) * 33 + K0 + 1] });
                hi.z = pack2h({ sh[R * 33 + K0 + 8],       sh[R * 33 + K0 + 9] });
                hi.w = pack2h({ sh[(R + 8) * 33 + K0 + 8], sh[(R + 8) * 33 + K0 + 9] });
                ((uint4*)dblk)[uu] = hi;
            }
        }
    }
}

// ---------------- column sums for comm ----------------
__global__ void colsum_part_k(const float* __restrict__ h, const float* __restrict__ alive,
                              float* __restrict__ part)
{
    int col = blockIdx.x * 128 + threadIdx.x;
    int r0 = blockIdx.y * 128;
    float s = 0.0f;
    for (int r = r0; r < r0 + 128; r++)
        s = fmaf(alive[r], h[(size_t)r * HID + col], s);
    part[blockIdx.y * HID + col] = s;
}
__global__ void colsum_red_k(const float* __restrict__ part, float* __restrict__ S)
{
    int c = blockIdx.x * 256 + threadIdx.x;
    float s = 0.0f;
#pragma unroll
    for (int i = 0; i < 16; i++) s += part[i * HID + c];
    S[c] = s;
}

// ---------------- misc ----------------
__global__ void nalive_k(const float* __restrict__ alive, float* __restrict__ out, int n)
{
    __shared__ float s[256];
    float v = 0.0f;
    for (int i = threadIdx.x; i < n; i += 256) v += alive[i];
    s[threadIdx.x] = v;
    __syncthreads();
    for (int st = 128; st > 0; st >>= 1) {
        if (threadIdx.x < st) s[threadIdx.x] += s[threadIdx.x + st];
        __syncthreads();
    }
    if (threadIdx.x == 0) *out = s[0];
}
// permuted bias: o[4*hc+g] = b_ih[g*HID+hc] + b_hh[g*HID+hc]
__global__ void bias_perm_k(const float* __restrict__ a, const float* __restrict__ b,
                            float* __restrict__ o, int n)
{
    int i = blockIdx.x * blockDim.x + threadIdx.x;
    if (i < n) {
        int g = i & 3, hc = i >> 2;
        o[i] = a[g * HID + hc] + b[g * HID + hc];
    }
}

// ---------------- head ----------------
__global__ void __launch_bounds__(256)
head_k(const float* __restrict__ h,
       const float* __restrict__ act_w, const float* __restrict__ act_b,
       const float* __restrict__ val_w, const float* __restrict__ val_b,
       float* __restrict__ out)
{
    const int n = blockIdx.x;
    const int tid = threadIdx.x;
    __shared__ float sh[HID];
    __shared__ float partial[4][ACT_D];
    __shared__ float vred[256];
    __shared__ float logits[ACT_D];

    const float* hr = h + (size_t)n * HID;
    for (int k = tid; k < HID; k += 256) sh[k] = hr[k];
    __syncthreads();

    const int col = tid & 63;
    const int part = tid >> 6;
    const float* w = act_w + (size_t)col * HID;
    float s = 0.0f;
    const int kbeg = part * (HID / 4);
    for (int k = kbeg; k < kbeg + HID / 4; k++) s = fmaf(sh[k], w[k], s);
    partial[part][col] = s;

    float v = 0.0f;
    for (int k = tid; k < HID; k += 256) v = fmaf(sh[k], val_w[k], v);
    vred[tid] = v;
    __syncthreads();

    if (tid < ACT_D)
        logits[tid] = partial[0][tid] + partial[1][tid] + partial[2][tid]
                    + partial[3][tid] + act_b[tid];

    for (int st = 128; st > 0; st >>= 1) {
        if (tid < st) vred[tid] += vred[tid + st];
        __syncthreads();
    }
    if (tid == 0) out[(size_t)NN_AG * ACT_D + n] = vred[0] + val_b[0];

    if (tid < 32) {
        float a = logits[tid], b = logits[tid + 32];
        float m = fmaxf(a, b);
#pragma unroll
        for (int o = 16; o > 0; o >>= 1) m = fmaxf(m, __shfl_xor_sync(0xffffffffu, m, o));
        float se = expf(a - m) + expf(b - m);
#pragma unroll
        for (int o = 16; o > 0; o >>= 1) se += __shfl_xor_sync(0xffffffffu, se, o);
        float lse = m + logf(se);
        out[(size_t)n * ACT_D + tid]      = a - lse;
        out[(size_t)n * ACT_D + tid + 32] = b - lse;
    }
}

// ---------------- launcher ----------------
extern "C" void kernel_launch(void* const* d_in, const int* in_sizes, int n_in,
                              void* d_out, int out_size)
{
    const float* obs    = (const float*)d_in[0];
    const float* alive  = (const float*)d_in[1];
    const float* enc_w  = (const float*)d_in[2];
    const float* enc_b  = (const float*)d_in[3];
    // d_in[4], d_in[5]: g_w, g_b — gate == 1 always (ceil(sigmoid), |logit| << 104)
    const float* w_ih   = (const float*)d_in[6];
    const float* w_hh   = (const float*)d_in[7];
    const float* b_ih   = (const float*)d_in[8];
    const float* b_hh   = (const float*)d_in[9];
    const float* act_w  = (const float*)d_in[10];
    const float* act_b  = (const float*)d_in[11];
    const float* val_w  = (const float*)d_in[12];
    const float* val_b  = (const float*)d_in[13];
    float* out = (float*)d_out;

    float *e, *ze, *h, *cell, *part, *S, *gu, *bsum, *nal;
    __half *Hp0, *Hp1, *Epk, *Aobs, *Wc, *Wip, *Wenc;
    cudaGetSymbolAddress((void**)&e,    g_e);
    cudaGetSymbolAddress((void**)&ze,   g_ze);
    cudaGetSymbolAddress((void**)&h,    g_h);
    cudaGetSymbolAddress((void**)&cell, g_cell);
    cudaGetSymbolAddress((void**)&part, g_part);
    cudaGetSymbolAddress((void**)&S,    g_S);
    cudaGetSymbolAddress((void**)&gu,   g_u);
    cudaGetSymbolAddress((void**)&bsum, g_bsum);
    cudaGetSymbolAddress((void**)&nal,  g_nalive);
    cudaGetSymbolAddress((void**)&Hp0,  g_Hp0);
    cudaGetSymbolAddress((void**)&Hp1,  g_Hp1);
    cudaGetSymbolAddress((void**)&Epk,  g_Epk);
    cudaGetSymbolAddress((void**)&Aobs, g_Aobs);
    cudaGetSymbolAddress((void**)&Wc,   g_Wc);
    cudaGetSymbolAddress((void**)&Wip,  g_Wip);
    cudaGetSymbolAddress((void**)&Wenc, g_Wenc);

    cudaFuncSetAttribute(gemm_fused<1>, cudaFuncAttributeMaxDynamicSharedMemorySize, SMEM_DYN);
    cudaFuncSetAttribute(gemm_fused<2>, cudaFuncAttributeMaxDynamicSharedMemorySize, SMEM_DYN);
    cudaFuncSetAttribute(gemm_fused<3>, cudaFuncAttributeMaxDynamicSharedMemorySize, SMEM_DYN);

    const size_t NH = (size_t)NN_AG * HID;
    const int unitsNH = (int)(NH / 8);

    nalive_k<<<1, 256>>>(alive, nal, NN_AG);
    bias_perm_k<<<(4 * HID + 255) / 256, 256>>>(b_ih, b_hh, bsum, 4 * HID);

    // packs
    {
        int unitsAobs = NN_AG * OBS_D / 8;
        pack_A<<<(unitsAobs + 255) / 256, 256>>>(obs, Aobs, OBS_D, 32, unitsAobs);
        int unitsWenc = HID * OBS_D / 4;
        pack_B<<<(unitsWenc + 255) / 256, 256>>>(enc_w, Wenc, OBS_D, 32, unitsWenc);
        int unitsWg = (4 * HID) * HID / 4;
        pack_Bg<<<(unitsWg + 255) / 256, 256>>>(w_ih, w_ih, nullptr, Wip, unitsWg);
        pack_Bg<<<(unitsWg + 255) / 256, 256>>>(w_hh, w_ih, nal, Wc, unitsWg);
    }

    // encoder: e = tanh(obs @ enc_w^T + enc_b)
    {
        dim3 grid(HID / 128, NN_AG / 128);
        gemm_fused<1><<<grid, 128, SMEM_DYN>>>(Aobs, Wenc, enc_b, e, 32, 32, 32, HID,
                                               nullptr, nullptr, nullptr,
                                               nullptr, nullptr, nullptr, 0);
    }
    // pack e; ze = e @ W_ih^T + bias (gate-permuted cols)
    pack_A<<<(unitsNH + 255) / 256, 256>>>(e, Epk, HID, 64, unitsNH);
    {
        dim3 grid(4 * HID / 128, NN_AG / 128);
        gemm_fused<3><<<grid, 128, SMEM_DYN>>>(Epk, Wip, bsum, ze, 64, 64, 64, 4 * HID,
                                               nullptr, nullptr, nullptr,
                                               nullptr, nullptr, nullptr, 0);
    }

    // iter 0: z = ze exactly (h=0, c=0); LSTM with cell=0; pack h -> Hp0
    lstm0_pack_k<<<(unitsNH + 255) / 256, 256>>>(ze, cell, h, Hp0);

    const dim3 gridZ(4 * HID / 128, NN_AG / 128);   // 64 x 16
    const dim3 gridCS(HID / 128, 16);
    __half* Hbuf[2] = { Hp0, Hp1 };

    for (int it = 1; it < ITERS; it++) {
        colsum_part_k<<<gridCS, 128>>>(h, alive, part);
        colsum_red_k<<<HID / 256, 256>>>(part, S);
        gemv_u_k<<<(4 * HID * 32 + 255) / 256, 256>>>(w_ih, S, gu);
        // z = h @ Wc^T + ze + inv*u, fused LSTM; pack h -> other buffer
        gemm_fused<2><<<gridZ, 128, SMEM_DYN>>>(Hbuf[(it - 1) & 1], Wc, nullptr, nullptr,
                                                64, 64, 64, 0,
                                                ze, gu, nal,
                                                cell, h, Hbuf[it & 1],
                                                (it < ITERS - 1) ? 1 : 0);
    }

    head_k<<<NN_AG, 256>>>(h, act_w, act_b, val_w, val_b, out);
}

// round 16
// speedup vs baseline: 1.1795x; 1.0184x over previous
#include <cuda_runtime.h>
#include <cuda_fp16.h>
#include <math.h>
#include <stdint.h>

// ---------------- problem constants ----------------
#define NN_AG 2048
#define HID   2048
#define OBS_D 1024
#define ACT_D 64
#define ITERS 3

// ---------------- device scratch ----------------
// fragment-major packed fp16; one 8KB block = 128 rows x 32 k
__device__ __align__(16) __half g_Hp0 [(size_t)16 * 64 * 4096];   // h pack, buffer 0
__device__ __align__(16) __half g_Hp1 [(size_t)16 * 64 * 4096];   // h pack, buffer 1
__device__ __align__(16) __half g_Epk [(size_t)16 * 64 * 4096];   // e pack (tanh enc)
__device__ __align__(16) __half g_Aobs[(size_t)16 * 32 * 4096];   // obs
__device__ __align__(16) __half g_Wc  [(size_t)64 * 64 * 4096];   // gate-perm (w_hh - inv*w_ih)
__device__ __align__(16) __half g_Wip [(size_t)64 * 64 * 4096];   // gate-perm w_ih
__device__ __align__(16) __half g_Wenc[(size_t)16 * 32 * 4096];   // enc_w
__device__ float g_ze  [(size_t)NN_AG * 4 * HID];   // e@W_ih^T + bias (gate-perm cols)
__device__ float g_h   [(size_t)NN_AG * HID];
__device__ float g_cell[(size_t)NN_AG * HID];
__device__ float g_part[16 * HID];
__device__ float g_S   [HID];
__device__ float g_u   [4 * HID];                   // W_ih @ S (gate-perm)
__device__ float g_bsum[4 * HID];
__device__ float g_nalive;

#define STAGE_B 16384          // [A 8K][B 8K], BK=32
#define NSTG 5
#define SMEM_DYN 84480         // epilogue: zbuf 67584 + sh 16896

__device__ __forceinline__ float sigf(float x) { return 1.0f / (1.0f + expf(-x)); }

// ---------------- low-level helpers ----------------
__device__ __forceinline__ uint32_t smem_u32(const void* p) {
    uint32_t a;
    asm("{ .reg .u64 t; cvta.to.shared.u64 t, %1; cvt.u32.u64 %0, t; }" : "=r"(a) : "l"(p));
    return a;
}
__device__ __forceinline__ void cpasync16(uint32_t d, const void* s) {
    asm volatile("cp.async.cg.shared.global [%0], [%1], 16;" :: "r"(d), "l"(s));
}
__device__ __forceinline__ uint4 lds128(uint32_t a) {
    uint4 v;
    asm volatile("ld.shared.v4.b32 {%0,%1,%2,%3}, [%4];"
                 : "=r"(v.x), "=r"(v.y), "=r"(v.z), "=r"(v.w) : "r"(a));
    return v;
}
__device__ __forceinline__ uint2 lds64(uint32_t a) {
    uint2 v;
    asm volatile("ld.shared.v2.b32 {%0,%1}, [%2];" : "=r"(v.x), "=r"(v.y) : "r"(a));
    return v;
}
__device__ __forceinline__ void mma16816(float* c, const uint32_t* a, const uint32_t* b) {
    asm volatile(
        "mma.sync.aligned.m16n8k16.row.col.f32.f16.f16.f32 "
        "{%0,%1,%2,%3}, {%4,%5,%6,%7}, {%8,%9}, {%0,%1,%2,%3};"
        : "+f"(c[0]), "+f"(c[1]), "+f"(c[2]), "+f"(c[3])
        : "r"(a[0]), "r"(a[1]), "r"(a[2]), "r"(a[3]), "r"(b[0]), "r"(b[1]));
}
__device__ __forceinline__ uint32_t hpack(__half x, __half y) {
    return (uint32_t)__half_as_ushort(x) | ((uint32_t)__half_as_ushort(y) << 16);
}
__device__ __forceinline__ uint32_t pack2h(float2 v) {
    return hpack(__float2half_rn(v.x), __float2half_rn(v.y));
}

// ---------------- pack kernels (fragment-major) ----------------
// A block: unit u16B; rows mt*16+(lane/4)(+8), k = ks*16+(lane%4)*2 (+8). 8 elems/unit.
__global__ void pack_A(const float* __restrict__ src, __half* __restrict__ dst,
                       int K, int nkcDst, int nunits)
{
    int u = blockIdx.x * 256 + threadIdx.x;
    if (u >= nunits) return;
    int lane = u & 31, mt = (u >> 5) & 7, ks = (u >> 8) & 1;
    int bk = u >> 9;
    int nkcSrc = K >> 5;
    int mtile = bk / nkcSrc, kchunk = bk - mtile * nkcSrc;
    int r0 = mtile * 128 + mt * 16 + (lane >> 2);
    int kb = kchunk * 32 + ks * 16 + (lane & 3) * 2;
    const float* s0 = src + (size_t)r0 * K + kb;
    const float* s1 = s0 + (size_t)8 * K;
    uint4 hi;
    hi.x = pack2h(*(const float2*)s0);
    hi.y = pack2h(*(const float2*)s1);
    hi.z = pack2h(*(const float2*)(s0 + 8));
    hi.w = pack2h(*(const float2*)(s1 + 8));
    size_t dblk = (size_t)mtile * nkcDst + kchunk;
    int unit = (ks * 8 + mt) * 32 + lane;
    ((uint4*)(dst + dblk * 4096))[unit] = hi;
}

// plain B pack (enc_w): n = nt*8+(lane/4), k = ks*16+(lane%4)*2 (+8). 4 elems/unit.
__global__ void pack_B(const float* __restrict__ src, __half* __restrict__ dst,
                       int K, int nkcDst, int nunits)
{
    int u = blockIdx.x * 256 + threadIdx.x;
    if (u >= nunits) return;
    int lane = u & 31, nt = (u >> 5) & 15, ks = (u >> 9) & 1;
    int bk = u >> 10;
    int nkcSrc = K >> 5;
    int ntile = bk / nkcSrc, kchunk = bk - ntile * nkcSrc;
    int n = ntile * 128 + nt * 8 + (lane >> 2);
    int kb = kchunk * 32 + ks * 16 + (lane & 3) * 2;
    const float* s = src + (size_t)n * K + kb;
    uint2 hi;
    hi.x = pack2h(*(const float2*)s);
    hi.y = pack2h(*(const float2*)(s + 8));
    size_t dblk = (size_t)ntile * nkcDst + kchunk;
    int unit = (ks * 16 + nt) * 32 + lane;
    ((uint2*)(dst + dblk * 4096))[unit] = hi;
}

// dual gate-interleaved weight pack: row n' = 4*hc+gate; reads w_ih + w_hh once;
// writes Wip = w_ih and Wc = w_hh - inv*w_ih. nkc = 64.
__global__ void pack_Bg2(const float* __restrict__ w_ih, const float* __restrict__ w_hh,
                         const float* __restrict__ nal,
                         __half* __restrict__ dWip, __half* __restrict__ dWc,
                         int nunits)
{
    int u = blockIdx.x * 256 + threadIdx.x;
    if (u >= nunits) return;
    int lane = u & 31, nt = (u >> 5) & 15, ks = (u >> 9) & 1;
    int bk = u >> 10;
    int ntile = bk >> 6, kchunk = bk & 63;
    int np = ntile * 128 + nt * 8 + (lane >> 2);
    int kb = kchunk * 32 + ks * 16 + (lane & 3) * 2;
    int gate = np & 3, hc = np >> 2;
    float sc = -1.0f / (*nal - 1.0f);
    size_t off = (size_t)(gate * HID + hc) * HID + kb;
    float2 a0 = *(const float2*)(w_ih + off);
    float2 a1 = *(const float2*)(w_ih + off + 8);
    float2 b0 = *(const float2*)(w_hh + off);
    float2 b1 = *(const float2*)(w_hh + off + 8);
    size_t dblk = (size_t)ntile * 64 + kchunk;
    int unit = (ks * 16 + nt) * 32 + lane;
    uint2 hi;
    hi.x = pack2h(a0);
    hi.y = pack2h(a1);
    ((uint2*)(dWip + dblk * 4096))[unit] = hi;
    hi.x = pack2h({ b0.x + sc * a0.x, b0.y + sc * a0.y });
    hi.y = pack2h({ b1.x + sc * a1.x, b1.y + sc * a1.y });
    ((uint2*)(dWc + dblk * 4096))[unit] = hi;
}

// ---------------- iter-0 LSTM: cell=sig(zi)tanh(zg), h=sig(zo)tanh(cell); pack h ----
__global__ void lstm0_pack_k(const float* __restrict__ ze, float* __restrict__ cell,
                             float* __restrict__ h, __half* __restrict__ dst)
{
    int u = blockIdx.x * 256 + threadIdx.x;   // NH/8 units
    int lane = u & 31, mt = (u >> 5) & 7, ks = (u >> 8) & 1;
    int bk = u >> 9;
    int mtile = bk >> 6, kchunk = bk & 63;
    int r0 = mtile * 128 + mt * 16 + (lane >> 2);
    int kb = kchunk * 32 + ks * 16 + (lane & 3) * 2;

    auto do2 = [&](int r, int hc) -> uint32_t {
        const float* zr = ze + (size_t)r * (4 * HID) + 4 * hc;
        float4 z0 = *(const float4*)zr;        // (i,f,g,o) for hc
        float4 z1 = *(const float4*)(zr + 4);  // for hc+1
        float c0 = sigf(z0.x) * tanhf(z0.z);
        float c1 = sigf(z1.x) * tanhf(z1.z);
        float h0 = sigf(z0.w) * tanhf(c0);
        float h1 = sigf(z1.w) * tanhf(c1);
        *(float2*)(cell + (size_t)r * HID + hc) = { c0, c1 };
        *(float2*)(h    + (size_t)r * HID + hc) = { h0, h1 };
        return pack2h({ h0, h1 });
    };
    uint4 hi;
    hi.x = do2(r0,     kb);
    hi.y = do2(r0 + 8, kb);
    hi.z = do2(r0,     kb + 8);
    hi.w = do2(r0 + 8, kb + 8);
    size_t dblk = (size_t)mtile * 64 + kchunk;
    int unit = (ks * 8 + mt) * 32 + lane;
    ((uint4*)(dst + dblk * 4096))[unit] = hi;
}

// ---------------- GEMV: u[n'] = dot(w_ih[gate*HID+hc], S), permuted n' ----------
__global__ void gemv_u_k(const float* __restrict__ w_ih, const float* __restrict__ S,
                         float* __restrict__ gu)
{
    int wrp = (blockIdx.x * 256 + threadIdx.x) >> 5;
    int lane = threadIdx.x & 31;
    if (wrp >= 4 * HID) return;
    int gate = wrp & 3, hc = wrp >> 2;
    const float4* row = (const float4*)(w_ih + (size_t)(gate * HID + hc) * HID);
    const float4* Sv = (const float4*)S;
    float s = 0.0f;
    for (int k = lane; k < HID / 4; k += 32) {
        float4 a = row[k], b = Sv[k];
        s += a.x * b.x + a.y * b.y + a.z * b.z + a.w * b.w;
    }
#pragma unroll
    for (int o = 16; o > 0; o >>= 1) s += __shfl_xor_sync(0xffffffffu, s, o);
    if (lane == 0) gu[wrp] = s;
}

// ---------------- GEMM: C(128x128) = A*B^T, fp16, 5-stage BK=32 pipeline ----------
// EPI=4: tanh(acc+bias) packed DIRECTLY from registers into Epk blocks (encoder).
// EPI=3: bias -> C (ze).
// EPI=2: z = acc + ze + inv*u, fused LSTM, pack h -> packDst block (MT*64+NT).
template<int EPI>
__global__ void __launch_bounds__(128, 2)
gemm_fused(const __half* __restrict__ Ap, const __half* __restrict__ Bp,
           const float* __restrict__ bias, float* __restrict__ C,
           int nkcA, int nkcB, int kcCount, int ldc,
           const float* __restrict__ ze, const float* __restrict__ gu,
           const float* __restrict__ nal,
           float* __restrict__ cell, float* __restrict__ hout,
           __half* __restrict__ packDst, int dopack)
{
    extern __shared__ __align__(16) char smem[];
    const uint32_t sb = smem_u32(smem);
    const int tid = threadIdx.x;
    const int MT = blockIdx.y, NT = blockIdx.x;
    const int wid = tid >> 5, lane = tid & 31;
    const int wm = wid >> 1, wn = wid & 1;

    float acc[4][8][4];
#pragma unroll
    for (int i = 0; i < 4; i++)
#pragma unroll
        for (int j = 0; j < 8; j++)
#pragma unroll
            for (int t = 0; t < 4; t++) acc[i][j][t] = 0.0f;

    auto issue = [&](int c) {
        const char* ab = (const char*)Ap + ((size_t)MT * nkcA + c) * 8192;
        const char* bb = (const char*)Bp + ((size_t)NT * nkcB + c) * 8192;
        uint32_t d = sb + (uint32_t)(c % NSTG) * STAGE_B;
#pragma unroll
        for (int i = 0; i < 4; i++) {
            uint32_t o = i * 2048 + tid * 16;
            cpasync16(d + o,        ab + o);   // A
            cpasync16(d + 8192 + o, bb + o);   // B
        }
        asm volatile("cp.async.commit_group;");
    };

    issue(0); issue(1); issue(2); issue(3);

    for (int vk = 0; vk < kcCount; vk++) {
        if (vk + 3 < kcCount)      asm volatile("cp.async.wait_group 3;");
        else if (vk + 2 < kcCount) asm volatile("cp.async.wait_group 2;");
        else if (vk + 1 < kcCount) asm volatile("cp.async.wait_group 1;");
        else                       asm volatile("cp.async.wait_group 0;");
        __syncthreads();
        if (vk + 4 < kcCount) issue(vk + 4);

        uint32_t st = sb + (uint32_t)(vk % NSTG) * STAGE_B;
#pragma unroll
        for (int ks = 0; ks < 2; ks++) {
            uint32_t a[4][4], b[8][2];
#pragma unroll
            for (int j = 0; j < 8; j++) {
                uint2 v = lds64(st + 8192u + (uint32_t)((ks * 16 + wn * 8 + j) * 256 + lane * 8));
                b[j][0] = v.x; b[j][1] = v.y;
            }
#pragma unroll
            for (int i = 0; i < 4; i++) {
                uint4 v = lds128(st + (uint32_t)((ks * 8 + wm * 4 + i) * 512 + lane * 16));
                a[i][0] = v.x; a[i][1] = v.y; a[i][2] = v.z; a[i][3] = v.w;
            }
#pragma unroll
            for (int i = 0; i < 4; i++)
#pragma unroll
                for (int j = 0; j < 8; j++) mma16816(acc[i][j], a[i], b[j]);
        }
    }

    if (EPI == 4) {
        // encoder: tanh(acc+bias) -> fragment pack (register-direct, no SMEM)
#pragma unroll
        for (int kcl = 0; kcl < 2; kcl++) {
            __half* dp = packDst + ((size_t)MT * 64 + NT * 4 + wn * 2 + kcl) * 4096;
#pragma unroll
            for (int ks = 0; ks < 2; ks++) {
                int j0 = kcl * 4 + ks * 2;
                int c0 = NT * 128 + wn * 64 + j0 * 8 + (lane & 3) * 2;
                float b0 = bias[c0], b1 = bias[c0 + 1];
                float b8 = bias[c0 + 8], b9 = bias[c0 + 9];
#pragma unroll
                for (int i = 0; i < 4; i++) {
                    uint4 hi;
                    hi.x = pack2h({ tanhf(acc[i][j0][0] + b0),     tanhf(acc[i][j0][1] + b1) });
                    hi.y = pack2h({ tanhf(acc[i][j0][2] + b0),     tanhf(acc[i][j0][3] + b1) });
                    hi.z = pack2h({ tanhf(acc[i][j0 + 1][0] + b8), tanhf(acc[i][j0 + 1][1] + b9) });
                    hi.w = pack2h({ tanhf(acc[i][j0 + 1][2] + b8), tanhf(acc[i][j0 + 1][3] + b9) });
                    ((uint4*)dp)[(ks * 8 + wm * 4 + i) * 32 + lane] = hi;
                }
            }
        }
    } else if (EPI == 3) {
        const int rowb = MT * 128 + wm * 64;
        const int colb = NT * 128 + wn * 64;
#pragma unroll
        for (int i = 0; i < 4; i++) {
            int r0 = rowb + i * 16 + (lane >> 2);
#pragma unroll
            for (int j = 0; j < 8; j++) {
                int c0 = colb + j * 8 + (lane & 3) * 2;
                float b0 = bias[c0], b1 = bias[c0 + 1];
                float2 v0 = { acc[i][j][0] + b0, acc[i][j][1] + b1 };
                float2 v1 = { acc[i][j][2] + b0, acc[i][j][3] + b1 };
                *(float2*)(C + (size_t)r0 * ldc + c0) = v0;
                *(float2*)(C + (size_t)(r0 + 8) * ldc + c0) = v1;
            }
        }
    } else {
        // ---- fused LSTM epilogue: z = acc + ze + inv*u ----
        __syncthreads();
        float* zbuf = (float*)smem;            // [128][132]
        const int colT = NT * 128;
        const float inv = 1.0f / (*nal - 1.0f);
#pragma unroll
        for (int i = 0; i < 4; i++) {
            int rr = wm * 64 + i * 16 + (lane >> 2);
            int gr = MT * 128 + rr;
#pragma unroll
            for (int j = 0; j < 8; j++) {
                int cc = wn * 64 + j * 8 + (lane & 3) * 2;
                const float* zer = ze + (size_t)gr * (4 * HID) + colT + cc;
                float2 ze0 = *(const float2*)zer;
                float2 ze1 = *(const float2*)(zer + (size_t)8 * (4 * HID));
                float u0 = inv * gu[colT + cc], u1 = inv * gu[colT + cc + 1];
                float2 v0 = { acc[i][j][0] + ze0.x + u0, acc[i][j][1] + ze0.y + u1 };
                float2 v1 = { acc[i][j][2] + ze1.x + u0, acc[i][j][3] + ze1.y + u1 };
                *(float2*)&zbuf[rr * 132 + cc] = v0;
                *(float2*)&zbuf[(rr + 8) * 132 + cc] = v1;
            }
        }
        __syncthreads();
        float* sh = (float*)(smem + 67584);    // [128][33]
        const int r = MT * 128 + tid;
        float* crow = cell + (size_t)r * HID + NT * 32;
        float* hrow = hout + (size_t)r * HID + NT * 32;
#pragma unroll
        for (int c4 = 0; c4 < 8; c4++) {
            float4 za = *(float4*)&zbuf[tid * 132 + c4 * 16 + 0];   // (i,f,g,o)
            float4 zb = *(float4*)&zbuf[tid * 132 + c4 * 16 + 4];
            float4 zc = *(float4*)&zbuf[tid * 132 + c4 * 16 + 8];
            float4 zd = *(float4*)&zbuf[tid * 132 + c4 * 16 + 12];
            float4 cold = *(const float4*)(crow + c4 * 4);
            float4 cn, hv;
            cn.x = sigf(za.y) * cold.x + sigf(za.x) * tanhf(za.z);
            cn.y = sigf(zb.y) * cold.y + sigf(zb.x) * tanhf(zb.z);
            cn.z = sigf(zc.y) * cold.z + sigf(zc.x) * tanhf(zc.z);
            cn.w = sigf(zd.y) * cold.w + sigf(zd.x) * tanhf(zd.z);
            hv.x = sigf(za.w) * tanhf(cn.x);
            hv.y = sigf(zb.w) * tanhf(cn.y);
            hv.z = sigf(zc.w) * tanhf(cn.z);
            hv.w = sigf(zd.w) * tanhf(cn.w);
            if (dopack) *(float4*)(crow + c4 * 4) = cn;   // dead on final iter
            *(float4*)(hrow + c4 * 4) = hv;
            sh[tid * 33 + c4 * 4 + 0] = hv.x;
            sh[tid * 33 + c4 * 4 + 1] = hv.y;
            sh[tid * 33 + c4 * 4 + 2] = hv.z;
            sh[tid * 33 + c4 * 4 + 3] = hv.w;
        }
        if (dopack) {
            __syncthreads();
            __half* dblk = packDst + ((size_t)MT * 64 + NT) * 4096;
#pragma unroll
            for (int t = 0; t < 4; t++) {
                int uu = tid + t * 128;
                int ll = uu & 31, mt2 = (uu >> 5) & 7, ks2 = uu >> 8;
                int R = mt2 * 16 + (ll >> 2), K0 = ks2 * 16 + (ll & 3) * 2;
                uint4 hi;
                hi.x = pack2h({ sh[R * 33 + K0],           sh[R * 33 + K0 + 1] });
                hi.y = pack2h({ sh[(R + 8) * 33 + K0],     sh[(R + 8) * 33 + K0 + 1] });
                hi.z = pack2h({ sh[R * 33 + K0 + 8],       sh[R * 33 + K0 + 9] });
                hi.w = pack2h({ sh[(R + 8) * 33 + K0 + 8], sh[(R + 8) * 33 + K0 + 9] });
                ((uint4*)dblk)[uu] = hi;
            }
        }
    }
}

// ---------------- column sums for comm ----------------
__global__ void colsum_part_k(const float* __restrict__ h, const float* __restrict__ alive,
                              float* __restrict__ part)
{
    int col = blockIdx.x * 128 + threadIdx.x;
    int r0 = blockIdx.y * 128;
    float s = 0.0f;
    for (int r = r0; r < r0 + 128; r++)
        s = fmaf(alive[r], h[(size_t)r * HID + col], s);
    part[blockIdx.y * HID + col] = s;
}
__global__ void colsum_red_k(const float* __restrict__ part, float* __restrict__ S)
{
    int c = blockIdx.x * 256 + threadIdx.x;
    float s = 0.0f;
#pragma unroll
    for (int i = 0; i < 16; i++) s += part[i * HID + c];
    S[c] = s;
}

// ---------------- misc ----------------
__global__ void nalive_k(const float* __restrict__ alive, float* __restrict__ out, int n)
{
    __shared__ float s[256];
    float v = 0.0f;
    for (int i = threadIdx.x; i < n; i += 256) v += alive[i];
    s[threadIdx.x] = v;
    __syncthreads();
    for (int st = 128; st > 0; st >>= 1) {
        if (threadIdx.x < st) s[threadIdx.x] += s[threadIdx.x + st];
        __syncthreads();
    }
    if (threadIdx.x == 0) *out = s[0];
}
// permuted bias: o[4*hc+g] = b_ih[g*HID+hc] + b_hh[g*HID+hc]
__global__ void bias_perm_k(const float* __restrict__ a, const float* __restrict__ b,
                            float* __restrict__ o, int n)
{
    int i = blockIdx.x * blockDim.x + threadIdx.x;
    if (i < n) {
        int g = i & 3, hc = i >> 2;
        o[i] = a[g * HID + hc] + b[g * HID + hc];
    }
}

// ---------------- head ----------------
__global__ void __launch_bounds__(256)
head_k(const float* __restrict__ h,
       const float* __restrict__ act_w, const float* __restrict__ act_b,
       const float* __restrict__ val_w, const float* __restrict__ val_b,
       float* __restrict__ out)
{
    const int n = blockIdx.x;
    const int tid = threadIdx.x;
    __shared__ float sh[HID];
    __shared__ float partial[4][ACT_D];
    __shared__ float vred[256];
    __shared__ float logits[ACT_D];

    const float* hr = h + (size_t)n * HID;
    for (int k = tid; k < HID; k += 256) sh[k] = hr[k];
    __syncthreads();

    const int col = tid & 63;
    const int part = tid >> 6;
    const float* w = act_w + (size_t)col * HID;
    float s = 0.0f;
    const int kbeg = part * (HID / 4);
    for (int k = kbeg; k < kbeg + HID / 4; k++) s = fmaf(sh[k], w[k], s);
    partial[part][col] = s;

    float v = 0.0f;
    for (int k = tid; k < HID; k += 256) v = fmaf(sh[k], val_w[k], v);
    vred[tid] = v;
    __syncthreads();

    if (tid < ACT_D)
        logits[tid] = partial[0][tid] + partial[1][tid] + partial[2][tid]
                    + partial[3][tid] + act_b[tid];

    for (int st = 128; st > 0; st >>= 1) {
        if (tid < st) vred[tid] += vred[tid + st];
        __syncthreads();
    }
    if (tid == 0) out[(size_t)NN_AG * ACT_D + n] = vred[0] + val_b[0];

    if (tid < 32) {
        float a = logits[tid], b = logits[tid + 32];
        float m = fmaxf(a, b);
#pragma unroll
        for (int o = 16; o > 0; o >>= 1) m = fmaxf(m, __shfl_xor_sync(0xffffffffu, m, o));
        float se = expf(a - m) + expf(b - m);
#pragma unroll
        for (int o = 16; o > 0; o >>= 1) se += __shfl_xor_sync(0xffffffffu, se, o);
        float lse = m + logf(se);
        out[(size_t)n * ACT_D + tid]      = a - lse;
        out[(size_t)n * ACT_D + tid + 32] = b - lse;
    }
}

// ---------------- launcher ----------------
extern "C" void kernel_launch(void* const* d_in, const int* in_sizes, int n_in,
                              void* d_out, int out_size)
{
    const float* obs    = (const float*)d_in[0];
    const float* alive  = (const float*)d_in[1];
    const float* enc_w  = (const float*)d_in[2];
    const float* enc_b  = (const float*)d_in[3];
    // d_in[4], d_in[5]: g_w, g_b — gate == 1 always (ceil(sigmoid), |logit| << 104)
    const float* w_ih   = (const float*)d_in[6];
    const float* w_hh   = (const float*)d_in[7];
    const float* b_ih   = (const float*)d_in[8];
    const float* b_hh   = (const float*)d_in[9];
    const float* act_w  = (const float*)d_in[10];
    const float* act_b  = (const float*)d_in[11];
    const float* val_w  = (const float*)d_in[12];
    const float* val_b  = (const float*)d_in[13];
    float* out = (float*)d_out;

    float *ze, *h, *cell, *part, *S, *gu, *bsum, *nal;
    __half *Hp0, *Hp1, *Epk, *Aobs, *Wc, *Wip, *Wenc;
    cudaGetSymbolAddress((void**)&ze,   g_ze);
    cudaGetSymbolAddress((void**)&h,    g_h);
    cudaGetSymbolAddress((void**)&cell, g_cell);
    cudaGetSymbolAddress((void**)&part, g_part);
    cudaGetSymbolAddress((void**)&S,    g_S);
    cudaGetSymbolAddress((void**)&gu,   g_u);
    cudaGetSymbolAddress((void**)&bsum, g_bsum);
    cudaGetSymbolAddress((void**)&nal,  g_nalive);
    cudaGetSymbolAddress((void**)&Hp0,  g_Hp0);
    cudaGetSymbolAddress((void**)&Hp1,  g_Hp1);
    cudaGetSymbolAddress((void**)&Epk,  g_Epk);
    cudaGetSymbolAddress((void**)&Aobs, g_Aobs);
    cudaGetSymbolAddress((void**)&Wc,   g_Wc);
    cudaGetSymbolAddress((void**)&Wip,  g_Wip);
    cudaGetSymbolAddress((void**)&Wenc, g_Wenc);

    cudaFuncSetAttribute(gemm_fused<2>, cudaFuncAttributeMaxDynamicSharedMemorySize, SMEM_DYN);
    cudaFuncSetAttribute(gemm_fused<3>, cudaFuncAttributeMaxDynamicSharedMemorySize, SMEM_DYN);
    cudaFuncSetAttribute(gemm_fused<4>, cudaFuncAttributeMaxDynamicSharedMemorySize, SMEM_DYN);

    const size_t NH = (size_t)NN_AG * HID;
    const int unitsNH = (int)(NH / 8);

    nalive_k<<<1, 256>>>(alive, nal, NN_AG);
    bias_perm_k<<<(4 * HID + 255) / 256, 256>>>(b_ih, b_hh, bsum, 4 * HID);

    // packs
    {
        int unitsAobs = NN_AG * OBS_D / 8;
        pack_A<<<(unitsAobs + 255) / 256, 256>>>(obs, Aobs, OBS_D, 32, unitsAobs);
        int unitsWenc = HID * OBS_D / 4;
        pack_B<<<(unitsWenc + 255) / 256, 256>>>(enc_w, Wenc, OBS_D, 32, unitsWenc);
        int unitsWg = (4 * HID) * HID / 4;
        pack_Bg2<<<(unitsWg + 255) / 256, 256>>>(w_ih, w_hh, nal, Wip, Wc, unitsWg);
    }

    // encoder: Epk = pack(tanh(obs @ enc_w^T + enc_b))  (register-direct pack)
    {
        dim3 grid(HID / 128, NN_AG / 128);
        gemm_fused<4><<<grid, 128, SMEM_DYN>>>(Aobs, Wenc, enc_b, nullptr, 32, 32, 32, 0,
                                               nullptr, nullptr, nullptr,
                                               nullptr, nullptr, Epk, 1);
    }
    // ze = e @ W_ih^T + bias (gate-permuted cols)
    {
        dim3 grid(4 * HID / 128, NN_AG / 128);
        gemm_fused<3><<<grid, 128, SMEM_DYN>>>(Epk, Wip, bsum, ze, 64, 64, 64, 4 * HID,
                                               nullptr, nullptr, nullptr,
                                               nullptr, nullptr, nullptr, 0);
    }

    // iter 0: z = ze exactly (h=0, c=0); LSTM with cell=0; pack h -> Hp0
    lstm0_pack_k<<<(unitsNH + 255) / 256, 256>>>(ze, cell, h, Hp0);

    const dim3 gridZ(4 * HID / 128, NN_AG / 128);   // 64 x 16
    const dim3 gridCS(HID / 128, 16);
    __half* Hbuf[2] = { Hp0, Hp1 };

    for (int it = 1; it < ITERS; it++) {
        colsum_part_k<<<gridCS, 128>>>(h, alive, part);
        colsum_red_k<<<HID / 256, 256>>>(part, S);
        gemv_u_k<<<(4 * HID * 32 + 255) / 256, 256>>>(w_ih, S, gu);
        // z = h @ Wc^T + ze + inv*u, fused LSTM; pack h -> other buffer
        gemm_fused<2><<<gridZ, 128, SMEM_DYN>>>(Hbuf[(it - 1) & 1], Wc, nullptr, nullptr,
                                                64, 64, 64, 0,
                                                ze, gu, nal,
                                                cell, h, Hbuf[it & 1],
                                                (it < ITERS - 1) ? 1 : 0);
    }

    head_k<<<NN_AG, 256>>>(h, act_w, act_b, val_w, val_b, out);
}

// round 17
// speedup vs baseline: 1.2074x; 1.0237x over previous
#include <cuda_runtime.h>
#include <cuda_fp16.h>
#include <math.h>
#include <stdint.h>

// ---------------- problem constants ----------------
#define NN_AG 2048
#define HID   2048
#define OBS_D 1024
#define ACT_D 64
#define ITERS 3

// ---------------- device scratch ----------------
// fragment-major packed fp16; one 8KB block = 128 rows x 32 k
__device__ __align__(16) __half g_Hp0 [(size_t)16 * 64 * 4096];   // h pack, buffer 0
__device__ __align__(16) __half g_Hp1 [(size_t)16 * 64 * 4096];   // h pack, buffer 1
__device__ __align__(16) __half g_Epk [(size_t)16 * 64 * 4096];   // e pack (tanh enc)
__device__ __align__(16) __half g_Aobs[(size_t)16 * 32 * 4096];   // obs
__device__ __align__(16) __half g_Wc  [(size_t)64 * 64 * 4096];   // gate-perm (w_hh - inv*w_ih)
__device__ __align__(16) __half g_Wip [(size_t)64 * 64 * 4096];   // gate-perm w_ih
__device__ __align__(16) __half g_Wenc[(size_t)16 * 32 * 4096];   // enc_w
__device__ float g_ze  [(size_t)NN_AG * 4 * HID];   // e@W_ih^T + bias (gate-perm cols)
__device__ float g_h   [(size_t)NN_AG * HID];
__device__ float g_cell[(size_t)NN_AG * HID];
__device__ float g_part[16 * HID];
__device__ float g_S   [HID];
__device__ float g_u   [4 * HID];                   // W_ih @ S (gate-perm)
__device__ float g_bsum[4 * HID];
__device__ float g_nalive;

#define STAGE_B 16384          // [A 8K][B 8K], BK=32
#define NSTG 5
#define SMEM_DYN 84480         // epilogue: zbuf 67584 + sh 16896

// fast transcendentals (MUFU.EX2-based; overflow-safe; rel err ~2^-22)
__device__ __forceinline__ float sigf(float x) {
    return __fdividef(1.0f, 1.0f + __expf(-x));
}
__device__ __forceinline__ float tanh_f(float x) {
    return 1.0f - __fdividef(2.0f, __expf(2.0f * x) + 1.0f);
}

// ---------------- low-level helpers ----------------
__device__ __forceinline__ uint32_t smem_u32(const void* p) {
    uint32_t a;
    asm("{ .reg .u64 t; cvta.to.shared.u64 t, %1; cvt.u32.u64 %0, t; }" : "=r"(a) : "l"(p));
    return a;
}
__device__ __forceinline__ void cpasync16(uint32_t d, const void* s) {
    asm volatile("cp.async.cg.shared.global [%0], [%1], 16;" :: "r"(d), "l"(s));
}
__device__ __forceinline__ uint4 lds128(uint32_t a) {
    uint4 v;
    asm volatile("ld.shared.v4.b32 {%0,%1,%2,%3}, [%4];"
                 : "=r"(v.x), "=r"(v.y), "=r"(v.z), "=r"(v.w) : "r"(a));
    return v;
}
__device__ __forceinline__ uint2 lds64(uint32_t a) {
    uint2 v;
    asm volatile("ld.shared.v2.b32 {%0,%1}, [%2];" : "=r"(v.x), "=r"(v.y) : "r"(a));
    return v;
}
__device__ __forceinline__ void mma16816(float* c, const uint32_t* a, const uint32_t* b) {
    asm volatile(
        "mma.sync.aligned.m16n8k16.row.col.f32.f16.f16.f32 "
        "{%0,%1,%2,%3}, {%4,%5,%6,%7}, {%8,%9}, {%0,%1,%2,%3};"
        : "+f"(c[0]), "+f"(c[1]), "+f"(c[2]), "+f"(c[3])
        : "r"(a[0]), "r"(a[1]), "r"(a[2]), "r"(a[3]), "r"(b[0]), "r"(b[1]));
}
__device__ __forceinline__ uint32_t hpack(__half x, __half y) {
    return (uint32_t)__half_as_ushort(x) | ((uint32_t)__half_as_ushort(y) << 16);
}
__device__ __forceinline__ uint32_t pack2h(float2 v) {
    return hpack(__float2half_rn(v.x), __float2half_rn(v.y));
}

// ---------------- pack kernels (fragment-major) ----------------
// A block: unit u16B; rows mt*16+(lane/4)(+8), k = ks*16+(lane%4)*2 (+8). 8 elems/unit.
__global__ void pack_A(const float* __restrict__ src, __half* __restrict__ dst,
                       int K, int nkcDst, int nunits)
{
    int u = blockIdx.x * 256 + threadIdx.x;
    if (u >= nunits) return;
    int lane = u & 31, mt = (u >> 5) & 7, ks = (u >> 8) & 1;
    int bk = u >> 9;
    int nkcSrc = K >> 5;
    int mtile = bk / nkcSrc, kchunk = bk - mtile * nkcSrc;
    int r0 = mtile * 128 + mt * 16 + (lane >> 2);
    int kb = kchunk * 32 + ks * 16 + (lane & 3) * 2;
    const float* s0 = src + (size_t)r0 * K + kb;
    const float* s1 = s0 + (size_t)8 * K;
    uint4 hi;
    hi.x = pack2h(*(const float2*)s0);
    hi.y = pack2h(*(const float2*)s1);
    hi.z = pack2h(*(const float2*)(s0 + 8));
    hi.w = pack2h(*(const float2*)(s1 + 8));
    size_t dblk = (size_t)mtile * nkcDst + kchunk;
    int unit = (ks * 8 + mt) * 32 + lane;
    ((uint4*)(dst + dblk * 4096))[unit] = hi;
}

// plain B pack (enc_w): n = nt*8+(lane/4), k = ks*16+(lane%4)*2 (+8). 4 elems/unit.
__global__ void pack_B(const float* __restrict__ src, __half* __restrict__ dst,
                       int K, int nkcDst, int nunits)
{
    int u = blockIdx.x * 256 + threadIdx.x;
    if (u >= nunits) return;
    int lane = u & 31, nt = (u >> 5) & 15, ks = (u >> 9) & 1;
    int bk = u >> 10;
    int nkcSrc = K >> 5;
    int ntile = bk / nkcSrc, kchunk = bk - ntile * nkcSrc;
    int n = ntile * 128 + nt * 8 + (lane >> 2);
    int kb = kchunk * 32 + ks * 16 + (lane & 3) * 2;
    const float* s = src + (size_t)n * K + kb;
    uint2 hi;
    hi.x = pack2h(*(const float2*)s);
    hi.y = pack2h(*(const float2*)(s + 8));
    size_t dblk = (size_t)ntile * nkcDst + kchunk;
    int unit = (ks * 16 + nt) * 32 + lane;
    ((uint2*)(dst + dblk * 4096))[unit] = hi;
}

// dual gate-interleaved weight pack: row n' = 4*hc+gate; reads w_ih + w_hh once;
// writes Wip = w_ih and Wc = w_hh - inv*w_ih. nkc = 64.
__global__ void pack_Bg2(const float* __restrict__ w_ih, const float* __restrict__ w_hh,
                         const float* __restrict__ nal,
                         __half* __restrict__ dWip, __half* __restrict__ dWc,
                         int nunits)
{
    int u = blockIdx.x * 256 + threadIdx.x;
    if (u >= nunits) return;
    int lane = u & 31, nt = (u >> 5) & 15, ks = (u >> 9) & 1;
    int bk = u >> 10;
    int ntile = bk >> 6, kchunk = bk & 63;
    int np = ntile * 128 + nt * 8 + (lane >> 2);
    int kb = kchunk * 32 + ks * 16 + (lane & 3) * 2;
    int gate = np & 3, hc = np >> 2;
    float sc = -1.0f / (*nal - 1.0f);
    size_t off = (size_t)(gate * HID + hc) * HID + kb;
    float2 a0 = *(const float2*)(w_ih + off);
    float2 a1 = *(const float2*)(w_ih + off + 8);
    float2 b0 = *(const float2*)(w_hh + off);
    float2 b1 = *(const float2*)(w_hh + off + 8);
    size_t dblk = (size_t)ntile * 64 + kchunk;
    int unit = (ks * 16 + nt) * 32 + lane;
    uint2 hi;
    hi.x = pack2h(a0);
    hi.y = pack2h(a1);
    ((uint2*)(dWip + dblk * 4096))[unit] = hi;
    hi.x = pack2h({ b0.x + sc * a0.x, b0.y + sc * a0.y });
    hi.y = pack2h({ b1.x + sc * a1.x, b1.y + sc * a1.y });
    ((uint2*)(dWc + dblk * 4096))[unit] = hi;
}

// ---------------- GEMV: u[n'] = dot(w_ih[gate*HID+hc], S), permuted n' ----------
__global__ void gemv_u_k(const float* __restrict__ w_ih, const float* __restrict__ S,
                         float* __restrict__ gu)
{
    int wrp = (blockIdx.x * 256 + threadIdx.x) >> 5;
    int lane = threadIdx.x & 31;
    if (wrp >= 4 * HID) return;
    int gate = wrp & 3, hc = wrp >> 2;
    const float4* row = (const float4*)(w_ih + (size_t)(gate * HID + hc) * HID);
    const float4* Sv = (const float4*)S;
    float s = 0.0f;
    for (int k = lane; k < HID / 4; k += 32) {
        float4 a = row[k], b = Sv[k];
        s += a.x * b.x + a.y * b.y + a.z * b.z + a.w * b.w;
    }
#pragma unroll
    for (int o = 16; o > 0; o >>= 1) s += __shfl_xor_sync(0xffffffffu, s, o);
    if (lane == 0) gu[wrp] = s;
}

// ---------------- GEMM: C(128x128) = A*B^T, fp16, 5-stage BK=32 pipeline ----------
// EPI=4: tanh(acc+bias) packed DIRECTLY from registers into Epk blocks (encoder).
// EPI=5: z = acc+bias; write ze; LSTM with cell==0; write cell/h; pack h (iter 0).
// EPI=2: z = acc + ze + inv*u, fused LSTM, pack h -> packDst block (MT*64+NT).
template<int EPI>
__global__ void __launch_bounds__(128, 2)
gemm_fused(const __half* __restrict__ Ap, const __half* __restrict__ Bp,
           const float* __restrict__ bias, float* __restrict__ C,
           int nkcA, int nkcB, int kcCount, int ldc,
           const float* __restrict__ ze, const float* __restrict__ gu,
           const float* __restrict__ nal,
           float* __restrict__ cell, float* __restrict__ hout,
           __half* __restrict__ packDst, int dopack)
{
    extern __shared__ __align__(16) char smem[];
    const uint32_t sb = smem_u32(smem);
    const int tid = threadIdx.x;
    const int MT = blockIdx.y, NT = blockIdx.x;
    const int wid = tid >> 5, lane = tid & 31;
    const int wm = wid >> 1, wn = wid & 1;

    float acc[4][8][4];
#pragma unroll
    for (int i = 0; i < 4; i++)
#pragma unroll
        for (int j = 0; j < 8; j++)
#pragma unroll
            for (int t = 0; t < 4; t++) acc[i][j][t] = 0.0f;

    auto issue = [&](int c) {
        const char* ab = (const char*)Ap + ((size_t)MT * nkcA + c) * 8192;
        const char* bb = (const char*)Bp + ((size_t)NT * nkcB + c) * 8192;
        uint32_t d = sb + (uint32_t)(c % NSTG) * STAGE_B;
#pragma unroll
        for (int i = 0; i < 4; i++) {
            uint32_t o = i * 2048 + tid * 16;
            cpasync16(d + o,        ab + o);   // A
            cpasync16(d + 8192 + o, bb + o);   // B
        }
        asm volatile("cp.async.commit_group;");
    };

    issue(0); issue(1); issue(2); issue(3);

    for (int vk = 0; vk < kcCount; vk++) {
        if (vk + 3 < kcCount)      asm volatile("cp.async.wait_group 3;");
        else if (vk + 2 < kcCount) asm volatile("cp.async.wait_group 2;");
        else if (vk + 1 < kcCount) asm volatile("cp.async.wait_group 1;");
        else                       asm volatile("cp.async.wait_group 0;");
        __syncthreads();
        if (vk + 4 < kcCount) issue(vk + 4);

        uint32_t st = sb + (uint32_t)(vk % NSTG) * STAGE_B;
#pragma unroll
        for (int ks = 0; ks < 2; ks++) {
            uint32_t a[4][4], b[8][2];
#pragma unroll
            for (int j = 0; j < 8; j++) {
                uint2 v = lds64(st + 8192u + (uint32_t)((ks * 16 + wn * 8 + j) * 256 + lane * 8));
                b[j][0] = v.x; b[j][1] = v.y;
            }
#pragma unroll
            for (int i = 0; i < 4; i++) {
                uint4 v = lds128(st + (uint32_t)((ks * 8 + wm * 4 + i) * 512 + lane * 16));
                a[i][0] = v.x; a[i][1] = v.y; a[i][2] = v.z; a[i][3] = v.w;
            }
#pragma unroll
            for (int i = 0; i < 4; i++)
#pragma unroll
                for (int j = 0; j < 8; j++) mma16816(acc[i][j], a[i], b[j]);
        }
    }

    if (EPI == 4) {
        // encoder: tanh(acc+bias) -> fragment pack (register-direct, no SMEM)
#pragma unroll
        for (int kcl = 0; kcl < 2; kcl++) {
            __half* dp = packDst + ((size_t)MT * 64 + NT * 4 + wn * 2 + kcl) * 4096;
#pragma unroll
            for (int ks = 0; ks < 2; ks++) {
                int j0 = kcl * 4 + ks * 2;
                int c0 = NT * 128 + wn * 64 + j0 * 8 + (lane & 3) * 2;
                float b0 = bias[c0], b1 = bias[c0 + 1];
                float b8 = bias[c0 + 8], b9 = bias[c0 + 9];
#pragma unroll
                for (int i = 0; i < 4; i++) {
                    uint4 hi;
                    hi.x = pack2h({ tanh_f(acc[i][j0][0] + b0),     tanh_f(acc[i][j0][1] + b1) });
                    hi.y = pack2h({ tanh_f(acc[i][j0][2] + b0),     tanh_f(acc[i][j0][3] + b1) });
                    hi.z = pack2h({ tanh_f(acc[i][j0 + 1][0] + b8), tanh_f(acc[i][j0 + 1][1] + b9) });
                    hi.w = pack2h({ tanh_f(acc[i][j0 + 1][2] + b8), tanh_f(acc[i][j0 + 1][3] + b9) });
                    ((uint4*)dp)[(ks * 8 + wm * 4 + i) * 32 + lane] = hi;
                }
            }
        }
    } else {
        // ---- fused LSTM epilogue (EPI==2: z=acc+ze+inv*u; EPI==5: z=acc+bias, write ze) ----
        __syncthreads();
        float* zbuf = (float*)smem;            // [128][132]
        const int colT = NT * 128;
        float inv = 0.0f;
        if (EPI == 2) inv = 1.0f / (*nal - 1.0f);
#pragma unroll
        for (int i = 0; i < 4; i++) {
            int rr = wm * 64 + i * 16 + (lane >> 2);
            int gr = MT * 128 + rr;
#pragma unroll
            for (int j = 0; j < 8; j++) {
                int cc = wn * 64 + j * 8 + (lane & 3) * 2;
                float2 v0, v1;
                if (EPI == 2) {
                    const float* zer = ze + (size_t)gr * (4 * HID) + colT + cc;
                    float2 ze0 = *(const float2*)zer;
                    float2 ze1 = *(const float2*)(zer + (size_t)8 * (4 * HID));
                    float u0 = inv * gu[colT + cc], u1 = inv * gu[colT + cc + 1];
                    v0 = { acc[i][j][0] + ze0.x + u0, acc[i][j][1] + ze0.y + u1 };
                    v1 = { acc[i][j][2] + ze1.x + u0, acc[i][j][3] + ze1.y + u1 };
                } else {
                    float b0 = bias[colT + cc], b1 = bias[colT + cc + 1];
                    v0 = { acc[i][j][0] + b0, acc[i][j][1] + b1 };
                    v1 = { acc[i][j][2] + b0, acc[i][j][3] + b1 };
                    float* zw = C + (size_t)gr * (4 * HID) + colT + cc;
                    *(float2*)zw = v0;
                    *(float2*)(zw + (size_t)8 * (4 * HID)) = v1;
                }
                *(float2*)&zbuf[rr * 132 + cc] = v0;
                *(float2*)&zbuf[(rr + 8) * 132 + cc] = v1;
            }
        }
        __syncthreads();
        float* sh = (float*)(smem + 67584);    // [128][33]
        const int r = MT * 128 + tid;
        float* crow = cell + (size_t)r * HID + NT * 32;
        float* hrow = hout + (size_t)r * HID + NT * 32;
#pragma unroll
        for (int c4 = 0; c4 < 8; c4++) {
            float4 za = *(float4*)&zbuf[tid * 132 + c4 * 16 + 0];   // (i,f,g,o)
            float4 zb = *(float4*)&zbuf[tid * 132 + c4 * 16 + 4];
            float4 zc = *(float4*)&zbuf[tid * 132 + c4 * 16 + 8];
            float4 zd = *(float4*)&zbuf[tid * 132 + c4 * 16 + 12];
            float4 cold = { 0.0f, 0.0f, 0.0f, 0.0f };
            if (EPI == 2) cold = *(const float4*)(crow + c4 * 4);
            float4 cn, hv;
            cn.x = sigf(za.y) * cold.x + sigf(za.x) * tanh_f(za.z);
            cn.y = sigf(zb.y) * cold.y + sigf(zb.x) * tanh_f(zb.z);
            cn.z = sigf(zc.y) * cold.z + sigf(zc.x) * tanh_f(zc.z);
            cn.w = sigf(zd.y) * cold.w + sigf(zd.x) * tanh_f(zd.z);
            hv.x = sigf(za.w) * tanh_f(cn.x);
            hv.y = sigf(zb.w) * tanh_f(cn.y);
            hv.z = sigf(zc.w) * tanh_f(cn.z);
            hv.w = sigf(zd.w) * tanh_f(cn.w);
            if (dopack) *(float4*)(crow + c4 * 4) = cn;   // dead on final iter
            *(float4*)(hrow + c4 * 4) = hv;
            sh[tid * 33 + c4 * 4 + 0] = hv.x;
            sh[tid * 33 + c4 * 4 + 1] = hv.y;
            sh[tid * 33 + c4 * 4 + 2] = hv.z;
            sh[tid * 33 + c4 * 4 + 3] = hv.w;
        }
        if (dopack) {
            __syncthreads();
            __half* dblk = packDst + ((size_t)MT * 64 + NT) * 4096;
#pragma unroll
            for (int t = 0; t < 4; t++) {
                int uu = tid + t * 128;
                int ll = uu & 31, mt2 = (uu >> 5) & 7, ks2 = uu >> 8;
                int R = mt2 * 16 + (ll >> 2), K0 = ks2 * 16 + (ll & 3) * 2;
                uint4 hi;
                hi.x = pack2h({ sh[R * 33 + K0],           sh[R * 33 + K0 + 1] });
                hi.y = pack2h({ sh[(R + 8) * 33 + K0],     sh[(R + 8) * 33 + K0 + 1] });
                hi.z = pack2h({ sh[R * 33 + K0 + 8],       sh[R * 33 + K0 + 9] });
                hi.w = pack2h({ sh[(R + 8) * 33 + K0 + 8], sh[(R + 8) * 33 + K0 + 9] });
                ((uint4*)dblk)[uu] = hi;
            }
        }
    }
}

// ---------------- column sums for comm ----------------
__global__ void colsum_part_k(const float* __restrict__ h, const float* __restrict__ alive,
                              float* __restrict__ part)
{
    int col = blockIdx.x * 128 + threadIdx.x;
    int r0 = blockIdx.y * 128;
    float s = 0.0f;
    for (int r = r0; r < r0 + 128; r++)
        s = fmaf(alive[r], h[(size_t)r * HID + col], s);
    part[blockIdx.y * HID + col] = s;
}
__global__ void colsum_red_k(const float* __restrict__ part, float* __restrict__ S)
{
    int c = blockIdx.x * 256 + threadIdx.x;
    float s = 0.0f;
#pragma unroll
    for (int i = 0; i < 16; i++) s += part[i * HID + c];
    S[c] = s;
}

// ---------------- misc ----------------
__global__ void nalive_k(const float* __restrict__ alive, float* __restrict__ out, int n)
{
    __shared__ float s[256];
    float v = 0.0f;
    for (int i = threadIdx.x; i < n; i += 256) v += alive[i];
    s[threadIdx.x] = v;
    __syncthreads();
    for (int st = 128; st > 0; st >>= 1) {
        if (threadIdx.x < st) s[threadIdx.x] += s[threadIdx.x + st];
        __syncthreads();
    }
    if (threadIdx.x == 0) *out = s[0];
}
// permuted bias: o[4*hc+g] = b_ih[g*HID+hc] + b_hh[g*HID+hc]
__global__ void bias_perm_k(const float* __restrict__ a, const float* __restrict__ b,
                            float* __restrict__ o, int n)
{
    int i = blockIdx.x * blockDim.x + threadIdx.x;
    if (i < n) {
        int g = i & 3, hc = i >> 2;
        o[i] = a[g * HID + hc] + b[g * HID + hc];
    }
}

// ---------------- head ----------------
__global__ void __launch_bounds__(256)
head_k(const float* __restrict__ h,
       const float* __restrict__ act_w, const float* __restrict__ act_b,
       const float* __restrict__ val_w, const float* __restrict__ val_b,
       float* __restrict__ out)
{
    const int n = blockIdx.x;
    const int tid = threadIdx.x;
    __shared__ float sh[HID];
    __shared__ float partial[4][ACT_D];
    __shared__ float vred[256];
    __shared__ float logits[ACT_D];

    const float* hr = h + (size_t)n * HID;
    for (int k = tid; k < HID; k += 256) sh[k] = hr[k];
    __syncthreads();

    const int col = tid & 63;
    const int part = tid >> 6;
    const float* w = act_w + (size_t)col * HID;
    float s = 0.0f;
    const int kbeg = part * (HID / 4);
    for (int k = kbeg; k < kbeg + HID / 4; k++) s = fmaf(sh[k], w[k], s);
    partial[part][col] = s;

    float v = 0.0f;
    for (int k = tid; k < HID; k += 256) v = fmaf(sh[k], val_w[k], v);
    vred[tid] = v;
    __syncthreads();

    if (tid < ACT_D)
        logits[tid] = partial[0][tid] + partial[1][tid] + partial[2][tid]
                    + partial[3][tid] + act_b[tid];

    for (int st = 128; st > 0; st >>= 1) {
        if (tid < st) vred[tid] += vred[tid + st];
        __syncthreads();
    }
    if (tid == 0) out[(size_t)NN_AG * ACT_D + n] = vred[0] + val_b[0];

    if (tid < 32) {
        float a = logits[tid], b = logits[tid + 32];
        float m = fmaxf(a, b);
#pragma unroll
        for (int o = 16; o > 0; o >>= 1) m = fmaxf(m, __shfl_xor_sync(0xffffffffu, m, o));
        float se = expf(a - m) + expf(b - m);
#pragma unroll
        for (int o = 16; o > 0; o >>= 1) se += __shfl_xor_sync(0xffffffffu, se, o);
        float lse = m + logf(se);
        out[(size_t)n * ACT_D + tid]      = a - lse;
        out[(size_t)n * ACT_D + tid + 32] = b - lse;
    }
}

// ---------------- launcher ----------------
extern "C" void kernel_launch(void* const* d_in, const int* in_sizes, int n_in,
                              void* d_out, int out_size)
{
    const float* obs    = (const float*)d_in[0];
    const float* alive  = (const float*)d_in[1];
    const float* enc_w  = (const float*)d_in[2];
    const float* enc_b  = (const float*)d_in[3];
    // d_in[4], d_in[5]: g_w, g_b — gate == 1 always (ceil(sigmoid), |logit| << 104)
    const float* w_ih   = (const float*)d_in[6];
    const float* w_hh   = (const float*)d_in[7];
    const float* b_ih   = (const float*)d_in[8];
    const float* b_hh   = (const float*)d_in[9];
    const float* act_w  = (const float*)d_in[10];
    const float* act_b  = (const float*)d_in[11];
    const float* val_w  = (const float*)d_in[12];
    const float* val_b  = (const float*)d_in[13];
    float* out = (float*)d_out;

    float *ze, *h, *cell, *part, *S, *gu, *bsum, *nal;
    __half *Hp0, *Hp1, *Epk, *Aobs, *Wc, *Wip, *Wenc;
    cudaGetSymbolAddress((void**)&ze,   g_ze);
    cudaGetSymbolAddress((void**)&h,    g_h);
    cudaGetSymbolAddress((void**)&cell, g_cell);
    cudaGetSymbolAddress((void**)&part, g_part);
    cudaGetSymbolAddress((void**)&S,    g_S);
    cudaGetSymbolAddress((void**)&gu,   g_u);
    cudaGetSymbolAddress((void**)&bsum, g_bsum);
    cudaGetSymbolAddress((void**)&nal,  g_nalive);
    cudaGetSymbolAddress((void**)&Hp0,  g_Hp0);
    cudaGetSymbolAddress((void**)&Hp1,  g_Hp1);
    cudaGetSymbolAddress((void**)&Epk,  g_Epk);
    cudaGetSymbolAddress((void**)&Aobs, g_Aobs);
    cudaGetSymbolAddress((void**)&Wc,   g_Wc);
    cudaGetSymbolAddress((void**)&Wip,  g_Wip);
    cudaGetSymbolAddress((void**)&Wenc, g_Wenc);

    cudaFuncSetAttribute(gemm_fused<2>, cudaFuncAttributeMaxDynamicSharedMemorySize, SMEM_DYN);
    cudaFuncSetAttribute(gemm_fused<4>, cudaFuncAttributeMaxDynamicSharedMemorySize, SMEM_DYN);
    cudaFuncSetAttribute(gemm_fused<5>, cudaFuncAttributeMaxDynamicSharedMemorySize, SMEM_DYN);

    nalive_k<<<1, 256>>>(alive, nal, NN_AG);
    bias_perm_k<<<(4 * HID + 255) / 256, 256>>>(b_ih, b_hh, bsum, 4 * HID);

    // packs
    {
        int unitsAobs = NN_AG * OBS_D / 8;
        pack_A<<<(unitsAobs + 255) / 256, 256>>>(obs, Aobs, OBS_D, 32, unitsAobs);
        int unitsWenc = HID * OBS_D / 4;
        pack_B<<<(unitsWenc + 255) / 256, 256>>>(enc_w, Wenc, OBS_D, 32, unitsWenc);
        int unitsWg = (4 * HID) * HID / 4;
        pack_Bg2<<<(unitsWg + 255) / 256, 256>>>(w_ih, w_hh, nal, Wip, Wc, unitsWg);
    }

    // encoder: Epk = pack(tanh(obs @ enc_w^T + enc_b))  (register-direct pack)
    {
        dim3 grid(HID / 128, NN_AG / 128);
        gemm_fused<4><<<grid, 128, SMEM_DYN>>>(Aobs, Wenc, enc_b, nullptr, 32, 32, 32, 0,
                                               nullptr, nullptr, nullptr,
                                               nullptr, nullptr, Epk, 1);
    }

    const dim3 gridZ(4 * HID / 128, NN_AG / 128);   // 64 x 16
    const dim3 gridCS(HID / 128, 16);
    __half* Hbuf[2] = { Hp0, Hp1 };

    // iter 0 fused: ze = e@W_ih^T + bias (written for later iters) + LSTM(cell=0)
    // + h/cell write + h-pack -> Hp0
    gemm_fused<5><<<gridZ, 128, SMEM_DYN>>>(Epk, Wip, bsum, ze, 64, 64, 64, 0,
                                            nullptr, nullptr, nullptr,
                                            cell, h, Hp0, 1);

    for (int it = 1; it < ITERS; it++) {
        colsum_part_k<<<gridCS, 128>>>(h, alive, part);
        colsum_red_k<<<HID / 256, 256>>>(part, S);
        gemv_u_k<<<(4 * HID * 32 + 255) / 256, 256>>>(w_ih, S, gu);
        // z = h @ Wc^T + ze + inv*u, fused LSTM; pack h -> other buffer
        gemm_fused<2><<<gridZ, 128, SMEM_DYN>>>(Hbuf[(it - 1) & 1], Wc, nullptr, nullptr,
                                                64, 64, 64, 0,
                                                ze, gu, nal,
                                                cell, h, Hbuf[it & 1],
                                                (it < ITERS - 1) ? 1 : 0);
    }

    head_k<<<NN_AG, 256>>>(h, act_w, act_b, val_w, val_b, out);
}